// round 3
// baseline (speedup 1.0000x reference)
#include <cuda_runtime.h>
#include <cstdint>

#define N_TOK 131072
#define BATCH 8
#define MCTX 256
#define DIM 512
#define CDIM 768
#define NH 8
#define HD 64
#define NB (N_TOK / BATCH)
#define ATT_SCALE 0.125f

// ---------------- scratch (device globals; no runtime allocation) ----------------
__device__ float g_f[(size_t)N_TOK * DIM];    // LayerNorm output (also residual)
__device__ float g_q[(size_t)N_TOK * DIM];    // Q projection
__device__ float g_k[BATCH * MCTX * DIM];     // K projection
__device__ float g_v[BATCH * MCTX * DIM];     // V projection
__device__ float g_att[(size_t)N_TOK * DIM];  // attention output

// ---------------- helpers ----------------
__device__ __forceinline__ uint32_t f2t(float x) {
    uint32_t r;
    asm("cvt.rna.tf32.f32 %0, %1;" : "=r"(r) : "f"(x));
    return r;
}
__device__ __forceinline__ float f2tf(float x) { return __uint_as_float(f2t(x)); }

__device__ __forceinline__ void mma8(float* c, const uint32_t* a, const uint32_t* b) {
    asm volatile(
        "mma.sync.aligned.m16n8k8.row.col.f32.tf32.tf32.f32 "
        "{%0,%1,%2,%3},{%4,%5,%6,%7},{%8,%9},{%0,%1,%2,%3};"
        : "+f"(c[0]), "+f"(c[1]), "+f"(c[2]), "+f"(c[3])
        : "r"(a[0]), "r"(a[1]), "r"(a[2]), "r"(a[3]), "r"(b[0]), "r"(b[1]));
}

// ---------------- LayerNorm: one warp per row ----------------
__global__ __launch_bounds__(256) void ln_kernel(
    const float* __restrict__ x, const float* __restrict__ g,
    const float* __restrict__ b, float* __restrict__ out)
{
    int row = blockIdx.x * 8 + (threadIdx.x >> 5);
    int lane = threadIdx.x & 31;
    const float4* xp = (const float4*)(x + (size_t)row * DIM);
    float4 v[4];
    float s = 0.f;
#pragma unroll
    for (int j = 0; j < 4; j++) {
        v[j] = xp[lane + j * 32];
        s += v[j].x + v[j].y + v[j].z + v[j].w;
    }
#pragma unroll
    for (int o = 16; o; o >>= 1) s += __shfl_xor_sync(0xffffffffu, s, o);
    float mu = s * (1.f / DIM);
    float s2 = 0.f;
#pragma unroll
    for (int j = 0; j < 4; j++) {
        float dx;
        dx = v[j].x - mu; s2 += dx * dx;
        dx = v[j].y - mu; s2 += dx * dx;
        dx = v[j].z - mu; s2 += dx * dx;
        dx = v[j].w - mu; s2 += dx * dx;
    }
#pragma unroll
    for (int o = 16; o; o >>= 1) s2 += __shfl_xor_sync(0xffffffffu, s2, o);
    float rstd = rsqrtf(s2 * (1.f / DIM) + 1e-5f);
    const float4* gp = (const float4*)g;
    const float4* bp = (const float4*)b;
    float4* op = (float4*)(out + (size_t)row * DIM);
#pragma unroll
    for (int j = 0; j < 4; j++) {
        int idx = lane + j * 32;
        float4 gg = gp[idx], bb = bp[idx], o;
        o.x = (v[j].x - mu) * rstd * gg.x + bb.x;
        o.y = (v[j].y - mu) * rstd * gg.y + bb.y;
        o.z = (v[j].z - mu) * rstd * gg.z + bb.z;
        o.w = (v[j].w - mu) * rstd * gg.w + bb.w;
        op[idx] = o;
    }
}

// ---------------- tf32 GEMM: out[M,N] = A[M,K] @ W[K,N] + bias (+resid) ----------------
// Block tile 128x128, K-tile 32, 8 warps (warp tile 64x32).
__global__ __launch_bounds__(256) void gemm_tf32(
    const float* __restrict__ A, const float* __restrict__ W,
    const float* __restrict__ bias, const float* __restrict__ resid,
    float* __restrict__ out, int Mr, int Nc, int K)
{
    __shared__ float As[128][36];   // [m][k], stride 36 -> conflict-free frag loads
    __shared__ float Bs[32][136];   // [k][n], stride 136 -> conflict-free frag loads
    const int tid = threadIdx.x;
    const int m0 = blockIdx.y * 128, n0 = blockIdx.x * 128;
    const int w = tid >> 5, lane = tid & 31, grp = lane >> 2, tq = lane & 3;
    const int wm = (w & 1) * 64, wn = (w >> 1) * 32;

    float acc[4][4][4];
#pragma unroll
    for (int i = 0; i < 4; i++)
#pragma unroll
        for (int j = 0; j < 4; j++)
#pragma unroll
            for (int r = 0; r < 4; r++) acc[i][j][r] = 0.f;

    for (int k0 = 0; k0 < K; k0 += 32) {
#pragma unroll
        for (int j = 0; j < 4; j++) {
            int lin = tid + j * 256;
            int m = lin >> 3, kq = (lin & 7) << 2;
            float4 va = *(const float4*)(A + (size_t)(m0 + m) * K + (k0 + kq));
            float4 sv = make_float4(f2tf(va.x), f2tf(va.y), f2tf(va.z), f2tf(va.w));
            *(float4*)&As[m][kq] = sv;
        }
#pragma unroll
        for (int j = 0; j < 4; j++) {
            int lin = tid + j * 256;
            int kk = lin >> 5, nq = (lin & 31) << 2;
            float4 vb = *(const float4*)(W + (size_t)(k0 + kk) * Nc + (n0 + nq));
            float4 sv = make_float4(f2tf(vb.x), f2tf(vb.y), f2tf(vb.z), f2tf(vb.w));
            *(float4*)&Bs[kk][nq] = sv;
        }
        __syncthreads();
#pragma unroll
        for (int kk = 0; kk < 32; kk += 8) {
            uint32_t a[4][4], b[4][2];
#pragma unroll
            for (int im = 0; im < 4; im++) {
                int r = wm + im * 16 + grp;
                a[im][0] = __float_as_uint(As[r][kk + tq]);
                a[im][1] = __float_as_uint(As[r + 8][kk + tq]);
                a[im][2] = __float_as_uint(As[r][kk + 4 + tq]);
                a[im][3] = __float_as_uint(As[r + 8][kk + 4 + tq]);
            }
#pragma unroll
            for (int jn = 0; jn < 4; jn++) {
                int c = wn + jn * 8 + grp;
                b[jn][0] = __float_as_uint(Bs[kk + tq][c]);
                b[jn][1] = __float_as_uint(Bs[kk + 4 + tq][c]);
            }
#pragma unroll
            for (int im = 0; im < 4; im++)
#pragma unroll
                for (int jn = 0; jn < 4; jn++)
                    mma8(acc[im][jn], a[im], b[jn]);
        }
        __syncthreads();
    }
#pragma unroll
    for (int im = 0; im < 4; im++)
#pragma unroll
        for (int jn = 0; jn < 4; jn++)
#pragma unroll
            for (int r = 0; r < 4; r++) {
                int row = m0 + wm + im * 16 + grp + ((r >> 1) << 3);
                int col = n0 + wn + jn * 8 + tq * 2 + (r & 1);
                float v = acc[im][jn][r] + bias[col];
                if (resid) v += resid[(size_t)row * Nc + col];
                out[(size_t)row * Nc + col] = v;
            }
}

// ---------------- fused attention per (batch, head, 64-query tile) ----------------
// S = Q K^T * scale; P = softmax(S); O = P V. K/V staged in SMEM, S aliases K region.
extern __shared__ float att_smem[];
__global__ __launch_bounds__(256) void attn_kernel(
    const float* __restrict__ Q, const float* __restrict__ Kg,
    const float* __restrict__ Vg, float* __restrict__ O)
{
    float* Qs = att_smem;              // [64][68]
    float* Ks = att_smem + 64 * 68;    // [256][68]  (aliased by Ss [64][260])
    float* Ss = Ks;
    float* VTs = Ks + 256 * 68;        // [64][260]  V transposed: [hd][m]

    int b = blockIdx.z, h = blockIdx.y, qt = blockIdx.x;
    int tid = threadIdx.x, w = tid >> 5, lane = tid & 31, grp = lane >> 2, tq = lane & 3;
    size_t qbase = ((size_t)(b * NB + qt * 64)) * DIM + h * HD;
    size_t kbase = ((size_t)(b * MCTX)) * DIM + h * HD;

    // Load Q tile (64x64)
#pragma unroll
    for (int j = 0; j < 4; j++) {
        int lin = tid + j * 256;
        int m = lin >> 4, c4 = (lin & 15) << 2;
        float4 v = *(const float4*)(Q + qbase + (size_t)m * DIM + c4);
        float4 sv = make_float4(f2tf(v.x), f2tf(v.y), f2tf(v.z), f2tf(v.w));
        *(float4*)&Qs[m * 68 + c4] = sv;
    }
    // Load K (256x64, as-is) and V (transposed -> [hd][m])
#pragma unroll
    for (int j = 0; j < 16; j++) {
        int lin = tid + j * 256;
        int m = lin >> 4, c4 = (lin & 15) << 2;
        float4 v = *(const float4*)(Kg + kbase + (size_t)m * DIM + c4);
        float4 sv = make_float4(f2tf(v.x), f2tf(v.y), f2tf(v.z), f2tf(v.w));
        *(float4*)&Ks[m * 68 + c4] = sv;
    }
#pragma unroll
    for (int j = 0; j < 16; j++) {
        int lin = tid + j * 256;
        int m = lin >> 4, c4 = (lin & 15) << 2;
        float4 v = *(const float4*)(Vg + kbase + (size_t)m * DIM + c4);
        VTs[(c4 + 0) * 260 + m] = f2tf(v.x);
        VTs[(c4 + 1) * 260 + m] = f2tf(v.y);
        VTs[(c4 + 2) * 260 + m] = f2tf(v.z);
        VTs[(c4 + 3) * 260 + m] = f2tf(v.w);
    }
    __syncthreads();

    // ---- S = Q @ K^T : warp grid 4(m) x 2(n); warp tile 16 x 128
    {
        int wm = (w & 3) * 16, wn = (w >> 2) * 128;
        float acc[16][4];
#pragma unroll
        for (int f = 0; f < 16; f++)
#pragma unroll
            for (int r = 0; r < 4; r++) acc[f][r] = 0.f;
#pragma unroll
        for (int kk = 0; kk < 64; kk += 8) {
            uint32_t a[4];
            int r = wm + grp;
            a[0] = __float_as_uint(Qs[r * 68 + kk + tq]);
            a[1] = __float_as_uint(Qs[(r + 8) * 68 + kk + tq]);
            a[2] = __float_as_uint(Qs[r * 68 + kk + 4 + tq]);
            a[3] = __float_as_uint(Qs[(r + 8) * 68 + kk + 4 + tq]);
#pragma unroll
            for (int f = 0; f < 16; f++) {
                uint32_t bb[2];
                int c = wn + f * 8 + grp;
                bb[0] = __float_as_uint(Ks[c * 68 + kk + tq]);
                bb[1] = __float_as_uint(Ks[c * 68 + kk + 4 + tq]);
                mma8(acc[f], a, bb);
            }
        }
        __syncthreads();  // everyone done reading Ks/Qs before S overwrites Ks
#pragma unroll
        for (int f = 0; f < 16; f++)
#pragma unroll
            for (int r = 0; r < 4; r++) {
                int row = wm + grp + ((r >> 1) << 3);
                int col = wn + f * 8 + tq * 2 + (r & 1);
                Ss[row * 260 + col] = acc[f][r] * ATT_SCALE;
            }
    }
    __syncthreads();

    // ---- softmax: warp w handles rows w*8 .. w*8+7 (256 cols each)
#pragma unroll
    for (int rr = 0; rr < 8; rr++) {
        int row = w * 8 + rr;
        float vals[8];
        float mx = -1e30f;
#pragma unroll
        for (int j = 0; j < 8; j++) {
            vals[j] = Ss[row * 260 + lane + j * 32];
            mx = fmaxf(mx, vals[j]);
        }
#pragma unroll
        for (int o = 16; o; o >>= 1) mx = fmaxf(mx, __shfl_xor_sync(0xffffffffu, mx, o));
        float sm = 0.f;
#pragma unroll
        for (int j = 0; j < 8; j++) {
            vals[j] = __expf(vals[j] - mx);
            sm += vals[j];
        }
#pragma unroll
        for (int o = 16; o; o >>= 1) sm += __shfl_xor_sync(0xffffffffu, sm, o);
        float inv = 1.f / sm;
#pragma unroll
        for (int j = 0; j < 8; j++)
            Ss[row * 260 + lane + j * 32] = f2tf(vals[j] * inv);
    }
    __syncthreads();

    // ---- O = P @ V : warp grid 4(m) x 2(n); warp tile 16 x 32
    {
        int wm = (w & 3) * 16, wn = (w >> 2) * 32;
        float acc[4][4];
#pragma unroll
        for (int f = 0; f < 4; f++)
#pragma unroll
            for (int r = 0; r < 4; r++) acc[f][r] = 0.f;
#pragma unroll
        for (int kk = 0; kk < 256; kk += 8) {
            uint32_t a[4];
            int r = wm + grp;
            a[0] = __float_as_uint(Ss[r * 260 + kk + tq]);
            a[1] = __float_as_uint(Ss[(r + 8) * 260 + kk + tq]);
            a[2] = __float_as_uint(Ss[r * 260 + kk + 4 + tq]);
            a[3] = __float_as_uint(Ss[(r + 8) * 260 + kk + 4 + tq]);
#pragma unroll
            for (int f = 0; f < 4; f++) {
                uint32_t bb[2];
                int c = wn + f * 8 + grp;
                bb[0] = __float_as_uint(VTs[c * 260 + kk + tq]);
                bb[1] = __float_as_uint(VTs[c * 260 + kk + 4 + tq]);
                mma8(acc[f], a, bb);
            }
        }
#pragma unroll
        for (int f = 0; f < 4; f++)
#pragma unroll
            for (int r = 0; r < 4; r++) {
                int row = wm + grp + ((r >> 1) << 3);
                int col = wn + f * 8 + tq * 2 + (r & 1);
                O[qbase + (size_t)row * DIM + col] = acc[f][r];
            }
    }
}

// ---------------- launcher ----------------
extern "C" void kernel_launch(void* const* d_in, const int* in_sizes, int n_in,
                              void* d_out, int out_size)
{
    const float* features = (const float*)d_in[0];
    // d_in[1] = batch_indices: sorted, equal counts -> batch = row / NB (arithmetic)
    const float* context = (const float*)d_in[2];
    const float* Wq = (const float*)d_in[3];
    const float* bq = (const float*)d_in[4];
    const float* Wk = (const float*)d_in[5];
    const float* bk = (const float*)d_in[6];
    const float* Wv = (const float*)d_in[7];
    const float* bv = (const float*)d_in[8];
    const float* Wout = (const float*)d_in[9];
    const float* bout = (const float*)d_in[10];
    const float* ln_g = (const float*)d_in[11];
    const float* ln_b = (const float*)d_in[12];
    float* out = (float*)d_out;

    float *f_p, *q_p, *k_p, *v_p, *att_p;
    cudaGetSymbolAddress((void**)&f_p, g_f);
    cudaGetSymbolAddress((void**)&q_p, g_q);
    cudaGetSymbolAddress((void**)&k_p, g_k);
    cudaGetSymbolAddress((void**)&v_p, g_v);
    cudaGetSymbolAddress((void**)&att_p, g_att);

    cudaFuncSetAttribute(attn_kernel, cudaFuncAttributeMaxDynamicSharedMemorySize, 153600);

    // 1. LayerNorm
    ln_kernel<<<N_TOK / 8, 256>>>(features, ln_g, ln_b, f_p);
    // 2. K, V projections: (B*M=2048, 768) @ (768, 512)
    gemm_tf32<<<dim3(DIM / 128, (BATCH * MCTX) / 128), 256>>>(
        context, Wk, bk, nullptr, k_p, BATCH * MCTX, DIM, CDIM);
    gemm_tf32<<<dim3(DIM / 128, (BATCH * MCTX) / 128), 256>>>(
        context, Wv, bv, nullptr, v_p, BATCH * MCTX, DIM, CDIM);
    // 3. Q projection: (131072, 512) @ (512, 512)
    gemm_tf32<<<dim3(DIM / 128, N_TOK / 128), 256>>>(
        f_p, Wq, bq, nullptr, q_p, N_TOK, DIM, DIM);
    // 4. Attention
    attn_kernel<<<dim3(NB / 64, NH, BATCH), 256, 153600>>>(q_p, k_p, v_p, att_p);
    // 5. Output projection + bias + residual
    gemm_tf32<<<dim3(DIM / 128, N_TOK / 128), 256>>>(
        att_p, Wout, bout, f_p, out, N_TOK, DIM, DIM);
}

// round 6
// speedup vs baseline: 1.5753x; 1.5753x over previous
#include <cuda_runtime.h>
#include <cstdint>

#define N_TOK 131072
#define BATCH 8
#define MCTX 256
#define DIM 512
#define CDIM 768
#define NH 8
#define HD 64
#define NB (N_TOK / BATCH)
#define ATT_SCALE 0.125f

// ---------------- scratch (device globals; no runtime allocation) ----------------
__device__ float g_f[(size_t)N_TOK * DIM];     // LayerNorm output fp32 (residual)
__device__ float g_ft[(size_t)N_TOK * DIM];    // LayerNorm output tf32-rounded
__device__ float g_q[(size_t)N_TOK * DIM];     // Q projection (tf32-rounded)
__device__ float g_k[BATCH * MCTX * DIM];      // K projection (tf32-rounded)
__device__ float g_v[BATCH * MCTX * DIM];      // V projection (tf32-rounded)
__device__ float g_att[(size_t)N_TOK * DIM];   // attention out (tf32-rounded)
__device__ float g_ctx_t[BATCH * MCTX * CDIM]; // context tf32-rounded
__device__ float g_wt[2 * CDIM * DIM + 2 * DIM * DIM]; // Wk,Wv,Wq,Wout tf32

#define WT_WK 0
#define WT_WV (CDIM * DIM)
#define WT_WQ (2 * CDIM * DIM)
#define WT_WOUT (2 * CDIM * DIM + DIM * DIM)

// ---------------- helpers ----------------
__device__ __forceinline__ float f2tf(float x) {
    uint32_t r;
    asm("cvt.rna.tf32.f32 %0, %1;" : "=r"(r) : "f"(x));
    return __uint_as_float(r);
}

__device__ __forceinline__ void mma8(float* c, const uint32_t* a, const uint32_t* b) {
    asm volatile(
        "mma.sync.aligned.m16n8k8.row.col.f32.tf32.tf32.f32 "
        "{%0,%1,%2,%3},{%4,%5,%6,%7},{%8,%9},{%0,%1,%2,%3};"
        : "+f"(c[0]), "+f"(c[1]), "+f"(c[2]), "+f"(c[3])
        : "r"(a[0]), "r"(a[1]), "r"(a[2]), "r"(a[3]), "r"(b[0]), "r"(b[1]));
}

__device__ __forceinline__ void cpa16(void* dst, const void* src) {
    uint32_t d = (uint32_t)__cvta_generic_to_shared(dst);
    asm volatile("cp.async.cg.shared.global [%0], [%1], 16;" :: "r"(d), "l"(src));
}
__device__ __forceinline__ void cp_commit() {
    asm volatile("cp.async.commit_group;");
}
template <int NN>
__device__ __forceinline__ void cp_wait() {
    asm volatile("cp.async.wait_group %0;" :: "n"(NN));
}

// ---------------- tf32 pre-round kernel ----------------
__global__ __launch_bounds__(256) void cvt_kernel(
    const float* __restrict__ src, float* __restrict__ dst, int n)
{
    int i = blockIdx.x * blockDim.x + threadIdx.x;
    int stride = gridDim.x * blockDim.x;
    for (; i < n; i += stride) dst[i] = f2tf(src[i]);
}

// ---------------- LayerNorm: one warp per row; writes fp32 + tf32 copies ----------------
__global__ __launch_bounds__(256) void ln_kernel(
    const float* __restrict__ x, const float* __restrict__ g,
    const float* __restrict__ b, float* __restrict__ out,
    float* __restrict__ out_t)
{
    int row = blockIdx.x * 8 + (threadIdx.x >> 5);
    int lane = threadIdx.x & 31;
    const float4* xp = (const float4*)(x + (size_t)row * DIM);
    float4 v[4];
    float s = 0.f;
#pragma unroll
    for (int j = 0; j < 4; j++) {
        v[j] = xp[lane + j * 32];
        s += v[j].x + v[j].y + v[j].z + v[j].w;
    }
#pragma unroll
    for (int o = 16; o; o >>= 1) s += __shfl_xor_sync(0xffffffffu, s, o);
    float mu = s * (1.f / DIM);
    float s2 = 0.f;
#pragma unroll
    for (int j = 0; j < 4; j++) {
        float dx;
        dx = v[j].x - mu; s2 += dx * dx;
        dx = v[j].y - mu; s2 += dx * dx;
        dx = v[j].z - mu; s2 += dx * dx;
        dx = v[j].w - mu; s2 += dx * dx;
    }
#pragma unroll
    for (int o = 16; o; o >>= 1) s2 += __shfl_xor_sync(0xffffffffu, s2, o);
    float rstd = rsqrtf(s2 * (1.f / DIM) + 1e-5f);
    const float4* gp = (const float4*)g;
    const float4* bp = (const float4*)b;
    float4* op = (float4*)(out + (size_t)row * DIM);
    float4* otp = (float4*)(out_t + (size_t)row * DIM);
#pragma unroll
    for (int j = 0; j < 4; j++) {
        int idx = lane + j * 32;
        float4 gg = gp[idx], bb = bp[idx], o, ot;
        o.x = (v[j].x - mu) * rstd * gg.x + bb.x;
        o.y = (v[j].y - mu) * rstd * gg.y + bb.y;
        o.z = (v[j].z - mu) * rstd * gg.z + bb.z;
        o.w = (v[j].w - mu) * rstd * gg.w + bb.w;
        op[idx] = o;
        ot.x = f2tf(o.x); ot.y = f2tf(o.y); ot.z = f2tf(o.z); ot.w = f2tf(o.w);
        otp[idx] = ot;
    }
}

// ---------------- tf32 GEMM (cp.async double-buffered, 64x64 warp tiles) -----------
// out[M,N] = A[M,K] @ W[K,N] + bias (+resid).  A and W pre-rounded tf32.
// Block 128x128, 128 threads, 4 warps (2m x 2n), warp tile 64x64, ktile 32.
__global__ __launch_bounds__(128, 2) void gemm_async(
    const float* __restrict__ A, const float* __restrict__ Wt,
    const float* __restrict__ bias, const float* __restrict__ resid,
    float* __restrict__ out, int K, int Nc, int round_out)
{
    extern __shared__ float sm[];
    float* As = sm;                 // [2][128][36]
    float* Bs = sm + 2 * 128 * 36;  // [2][32][136]
    const int tid = threadIdx.x;
    const int w = tid >> 5, lane = tid & 31, grp = lane >> 2, tq = lane & 3;
    const int wm = (w & 1) * 64, wn = (w >> 1) * 64;
    const int m0 = blockIdx.y * 128, n0 = blockIdx.x * 128;

    float acc[4][8][4];
#pragma unroll
    for (int i = 0; i < 4; i++)
#pragma unroll
        for (int j = 0; j < 8; j++)
#pragma unroll
            for (int r = 0; r < 4; r++) acc[i][j][r] = 0.f;

    auto load_tile = [&](int buf, int k0) {
#pragma unroll
        for (int j = 0; j < 8; j++) {
            int lin = tid + j * 128;
            int m = lin >> 3, kq = (lin & 7) << 2;
            cpa16(As + buf * 4608 + m * 36 + kq,
                  A + (size_t)(m0 + m) * K + k0 + kq);
        }
#pragma unroll
        for (int j = 0; j < 8; j++) {
            int lin = tid + j * 128;
            int kk = lin >> 5, nq = (lin & 31) << 2;
            cpa16(Bs + buf * 4352 + kk * 136 + nq,
                  Wt + (size_t)(k0 + kk) * Nc + n0 + nq);
        }
    };

    load_tile(0, 0);
    cp_commit();
    load_tile(1, 32);
    cp_commit();

    const int KT = K / 32;
    for (int kt = 0; kt < KT; kt++) {
        cp_wait<1>();
        __syncthreads();
        const float* Ab = As + (kt & 1) * 4608;
        const float* Bb = Bs + (kt & 1) * 4352;
#pragma unroll
        for (int kk = 0; kk < 32; kk += 8) {
            uint32_t a[4][4], b[8][2];
#pragma unroll
            for (int mf = 0; mf < 4; mf++) {
                const float* ar = Ab + (wm + mf * 16 + grp) * 36;
                a[mf][0] = __float_as_uint(ar[kk + tq]);
                a[mf][1] = __float_as_uint(ar[8 * 36 + kk + tq]);
                a[mf][2] = __float_as_uint(ar[kk + 4 + tq]);
                a[mf][3] = __float_as_uint(ar[8 * 36 + kk + 4 + tq]);
            }
#pragma unroll
            for (int nf = 0; nf < 8; nf++) {
                int c = wn + nf * 8 + grp;
                b[nf][0] = __float_as_uint(Bb[(kk + tq) * 136 + c]);
                b[nf][1] = __float_as_uint(Bb[(kk + 4 + tq) * 136 + c]);
            }
#pragma unroll
            for (int mf = 0; mf < 4; mf++)
#pragma unroll
                for (int nf = 0; nf < 8; nf++)
                    mma8(acc[mf][nf], a[mf], b[nf]);
        }
        __syncthreads();
        if (kt + 2 < KT) load_tile(kt & 1, (kt + 2) * 32);
        cp_commit();
    }

    // epilogue
#pragma unroll
    for (int mf = 0; mf < 4; mf++) {
        int r = m0 + wm + mf * 16 + grp;
#pragma unroll
        for (int nf = 0; nf < 8; nf++) {
            int c = n0 + wn + nf * 8 + tq * 2;
            float b0 = bias[c], b1 = bias[c + 1];
            float v0 = acc[mf][nf][0] + b0, v1 = acc[mf][nf][1] + b1;
            float v2 = acc[mf][nf][2] + b0, v3 = acc[mf][nf][3] + b1;
            if (resid) {
                const float* r0p = resid + (size_t)r * Nc + c;
                const float* r1p = resid + (size_t)(r + 8) * Nc + c;
                v0 += r0p[0]; v1 += r0p[1];
                v2 += r1p[0]; v3 += r1p[1];
            }
            if (round_out) {
                v0 = f2tf(v0); v1 = f2tf(v1); v2 = f2tf(v2); v3 = f2tf(v3);
            }
            *(float2*)&out[(size_t)r * Nc + c] = make_float2(v0, v1);
            *(float2*)&out[(size_t)(r + 8) * Nc + c] = make_float2(v2, v3);
        }
    }
}

// ---------------- fused attention: 128-query tile, register softmax -----------------
// Each warp owns 16 q-rows x all 256 ctx cols; S lives entirely in registers;
// P converted to A-fragments with quad shuffles; one __syncthreads total.
extern __shared__ float att_sm[];
__global__ __launch_bounds__(256, 1) void attn_kernel(
    const float* __restrict__ Q, const float* __restrict__ Kg,
    const float* __restrict__ Vg, float* __restrict__ O)
{
    float* Qs = att_sm;              // [128][68]
    float* Ks = att_sm + 128 * 68;   // [256][68]
    float* Vs = Ks + 256 * 68;       // [256][72]

    int b = blockIdx.z, h = blockIdx.y, qt = blockIdx.x;
    int tid = threadIdx.x, w = tid >> 5, lane = tid & 31, grp = lane >> 2, tq = lane & 3;
    size_t qbase = ((size_t)(b * NB + qt * 128)) * DIM + h * HD;
    size_t kbase = ((size_t)(b * MCTX)) * DIM + h * HD;

    // async tile loads (inputs pre-rounded tf32, plain copies)
#pragma unroll
    for (int j = 0; j < 8; j++) {
        int lin = tid + j * 256;
        int m = lin >> 4, c4 = (lin & 15) << 2;
        cpa16(Qs + m * 68 + c4, Q + qbase + (size_t)m * DIM + c4);
    }
#pragma unroll
    for (int j = 0; j < 16; j++) {
        int lin = tid + j * 256;
        int m = lin >> 4, c4 = (lin & 15) << 2;
        cpa16(Ks + m * 68 + c4, Kg + kbase + (size_t)m * DIM + c4);
    }
#pragma unroll
    for (int j = 0; j < 16; j++) {
        int lin = tid + j * 256;
        int m = lin >> 4, c4 = (lin & 15) << 2;
        cpa16(Vs + m * 72 + c4, Vg + kbase + (size_t)m * DIM + c4);
    }
    cp_commit();
    cp_wait<0>();
    __syncthreads();

    const int r0 = w * 16;

    // ---- S = Q @ K^T in registers: p[f][r] covers rows r0+grp(+8), cols f*8+tq*2+{0,1}
    float p[32][4];
#pragma unroll
    for (int f = 0; f < 32; f++)
#pragma unroll
        for (int r = 0; r < 4; r++) p[f][r] = 0.f;

#pragma unroll
    for (int kk = 0; kk < 64; kk += 8) {
        uint32_t a[4];
        const float* qr = Qs + (r0 + grp) * 68;
        a[0] = __float_as_uint(qr[kk + tq]);
        a[1] = __float_as_uint(qr[8 * 68 + kk + tq]);
        a[2] = __float_as_uint(qr[kk + 4 + tq]);
        a[3] = __float_as_uint(qr[8 * 68 + kk + 4 + tq]);
#pragma unroll
        for (int f = 0; f < 32; f++) {
            uint32_t bb[2];
            const float* kr = Ks + (f * 8 + grp) * 68;
            bb[0] = __float_as_uint(kr[kk + tq]);
            bb[1] = __float_as_uint(kr[kk + 4 + tq]);
            mma8(p[f], a, bb);
        }
    }

    // ---- softmax in registers (scale folded into exp; rows reduce within quad)
    float mxA = -1e30f, mxB = -1e30f;
#pragma unroll
    for (int f = 0; f < 32; f++) {
        mxA = fmaxf(mxA, fmaxf(p[f][0], p[f][1]));
        mxB = fmaxf(mxB, fmaxf(p[f][2], p[f][3]));
    }
    mxA = fmaxf(mxA, __shfl_xor_sync(0xffffffffu, mxA, 1));
    mxA = fmaxf(mxA, __shfl_xor_sync(0xffffffffu, mxA, 2));
    mxB = fmaxf(mxB, __shfl_xor_sync(0xffffffffu, mxB, 1));
    mxB = fmaxf(mxB, __shfl_xor_sync(0xffffffffu, mxB, 2));
    float sA = 0.f, sB = 0.f;
#pragma unroll
    for (int f = 0; f < 32; f++) {
        p[f][0] = __expf(ATT_SCALE * (p[f][0] - mxA)); sA += p[f][0];
        p[f][1] = __expf(ATT_SCALE * (p[f][1] - mxA)); sA += p[f][1];
        p[f][2] = __expf(ATT_SCALE * (p[f][2] - mxB)); sB += p[f][2];
        p[f][3] = __expf(ATT_SCALE * (p[f][3] - mxB)); sB += p[f][3];
    }
    sA += __shfl_xor_sync(0xffffffffu, sA, 1);
    sA += __shfl_xor_sync(0xffffffffu, sA, 2);
    sB += __shfl_xor_sync(0xffffffffu, sB, 1);
    sB += __shfl_xor_sync(0xffffffffu, sB, 2);
    float iA = 1.f / sA, iB = 1.f / sB;
#pragma unroll
    for (int f = 0; f < 32; f++) {
        p[f][0] = f2tf(p[f][0] * iA);
        p[f][1] = f2tf(p[f][1] * iA);
        p[f][2] = f2tf(p[f][2] * iB);
        p[f][3] = f2tf(p[f][3] * iB);
    }

    // ---- O = P @ V : P fragments built by quad shuffles, V from smem
    float o[8][4];
#pragma unroll
    for (int f = 0; f < 8; f++)
#pragma unroll
        for (int r = 0; r < 4; r++) o[f][r] = 0.f;

    const int l0 = (lane & 28) | (tq >> 1);
    const int sel = tq & 1;
#pragma unroll
    for (int kt = 0; kt < 32; kt++) {
        float v0 = __shfl_sync(0xffffffffu, p[kt][0], l0);
        float v1 = __shfl_sync(0xffffffffu, p[kt][1], l0);
        float v2 = __shfl_sync(0xffffffffu, p[kt][2], l0);
        float v3 = __shfl_sync(0xffffffffu, p[kt][3], l0);
        float u0 = __shfl_sync(0xffffffffu, p[kt][0], l0 + 2);
        float u1 = __shfl_sync(0xffffffffu, p[kt][1], l0 + 2);
        float u2 = __shfl_sync(0xffffffffu, p[kt][2], l0 + 2);
        float u3 = __shfl_sync(0xffffffffu, p[kt][3], l0 + 2);
        uint32_t a[4];
        a[0] = __float_as_uint(sel ? v1 : v0);
        a[1] = __float_as_uint(sel ? v3 : v2);
        a[2] = __float_as_uint(sel ? u1 : u0);
        a[3] = __float_as_uint(sel ? u3 : u2);
#pragma unroll
        for (int f2 = 0; f2 < 8; f2++) {
            uint32_t bb[2];
            const float* vr = Vs + (kt * 8 + tq) * 72 + f2 * 8 + grp;
            bb[0] = __float_as_uint(vr[0]);
            bb[1] = __float_as_uint(vr[4 * 72]);
            mma8(o[f2], a, bb);
        }
    }

    // epilogue: write tf32-rounded attention output
#pragma unroll
    for (int f2 = 0; f2 < 8; f2++) {
        int col = f2 * 8 + tq * 2;
        float2 t0 = make_float2(f2tf(o[f2][0]), f2tf(o[f2][1]));
        *(float2*)&O[qbase + (size_t)(r0 + grp) * DIM + col] = t0;
        float2 t1 = make_float2(f2tf(o[f2][2]), f2tf(o[f2][3]));
        *(float2*)&O[qbase + (size_t)(r0 + grp + 8) * DIM + col] = t1;
    }
}

// ---------------- launcher ----------------
extern "C" void kernel_launch(void* const* d_in, const int* in_sizes, int n_in,
                              void* d_out, int out_size)
{
    const float* features = (const float*)d_in[0];
    // d_in[1] = batch_indices: sorted, equal counts -> batch = row / NB (arithmetic)
    const float* context = (const float*)d_in[2];
    const float* Wq = (const float*)d_in[3];
    const float* bq = (const float*)d_in[4];
    const float* Wk = (const float*)d_in[5];
    const float* bk = (const float*)d_in[6];
    const float* Wv = (const float*)d_in[7];
    const float* bv = (const float*)d_in[8];
    const float* Wout = (const float*)d_in[9];
    const float* bout = (const float*)d_in[10];
    const float* ln_g = (const float*)d_in[11];
    const float* ln_b = (const float*)d_in[12];
    float* out = (float*)d_out;

    float *f_p, *ft_p, *q_p, *k_p, *v_p, *att_p, *ctx_p, *wt_p;
    cudaGetSymbolAddress((void**)&f_p, g_f);
    cudaGetSymbolAddress((void**)&ft_p, g_ft);
    cudaGetSymbolAddress((void**)&q_p, g_q);
    cudaGetSymbolAddress((void**)&k_p, g_k);
    cudaGetSymbolAddress((void**)&v_p, g_v);
    cudaGetSymbolAddress((void**)&att_p, g_att);
    cudaGetSymbolAddress((void**)&ctx_p, g_ctx_t);
    cudaGetSymbolAddress((void**)&wt_p, g_wt);

    cudaFuncSetAttribute(gemm_async, cudaFuncAttributeMaxDynamicSharedMemorySize, 71680);
    cudaFuncSetAttribute(attn_kernel, cudaFuncAttributeMaxDynamicSharedMemorySize, 178176);

    // tf32 pre-rounding of context + weights
    cvt_kernel<<<2048, 256>>>(context, ctx_p, BATCH * MCTX * CDIM);
    cvt_kernel<<<1024, 256>>>(Wk, wt_p + WT_WK, CDIM * DIM);
    cvt_kernel<<<1024, 256>>>(Wv, wt_p + WT_WV, CDIM * DIM);
    cvt_kernel<<<1024, 256>>>(Wq, wt_p + WT_WQ, DIM * DIM);
    cvt_kernel<<<1024, 256>>>(Wout, wt_p + WT_WOUT, DIM * DIM);

    // 1. LayerNorm (fp32 + tf32 outputs)
    ln_kernel<<<N_TOK / 8, 256>>>(features, ln_g, ln_b, f_p, ft_p);
    // 2. K, V projections: (2048, 768) @ (768, 512), tf32-rounded outputs
    gemm_async<<<dim3(DIM / 128, (BATCH * MCTX) / 128), 128, 71680>>>(
        ctx_p, wt_p + WT_WK, bk, nullptr, k_p, CDIM, DIM, 1);
    gemm_async<<<dim3(DIM / 128, (BATCH * MCTX) / 128), 128, 71680>>>(
        ctx_p, wt_p + WT_WV, bv, nullptr, v_p, CDIM, DIM, 1);
    // 3. Q projection: (131072, 512) @ (512, 512), tf32-rounded output
    gemm_async<<<dim3(DIM / 128, N_TOK / 128), 128, 71680>>>(
        ft_p, wt_p + WT_WQ, bq, nullptr, q_p, DIM, DIM, 1);
    // 4. Attention
    attn_kernel<<<dim3(NB / 128, NH, BATCH), 256, 178176>>>(q_p, k_p, v_p, att_p);
    // 5. Output projection + bias + residual (fp32 output)
    gemm_async<<<dim3(DIM / 128, N_TOK / 128), 128, 71680>>>(
        att_p, wt_p + WT_WOUT, bout, f_p, out, DIM, DIM, 0);
}

// round 9
// speedup vs baseline: 2.0295x; 1.2883x over previous
#include <cuda_runtime.h>
#include <cuda_fp16.h>
#include <cstdint>

#define N_TOK 131072
#define BATCH 8
#define MCTX 256
#define DIM 512
#define CDIM 768
#define NH 8
#define HD 64
#define NB (N_TOK / BATCH)
#define ATT_SCALE 0.125f

// ---------------- scratch (device globals; no runtime allocation) ----------------
__device__ float  g_f[(size_t)N_TOK * DIM];      // LayerNorm output fp32 (residual)
__device__ __half g_fh[(size_t)N_TOK * DIM];     // LayerNorm output fp16
__device__ __half g_q[(size_t)N_TOK * DIM];      // Q projection fp16
__device__ __half g_k[BATCH * MCTX * DIM];       // K projection fp16
__device__ __half g_v[BATCH * MCTX * DIM];       // V projection fp16
__device__ __half g_att[(size_t)N_TOK * DIM];    // attention out fp16
__device__ __half g_ctx[BATCH * MCTX * CDIM];    // context fp16
__device__ __half g_wt[2 * CDIM * DIM + 2 * DIM * DIM]; // WkT,WvT,WqT,WoutT fp16, K-major [N][K]

#define WT_WK 0
#define WT_WV (CDIM * DIM)
#define WT_WQ (2 * CDIM * DIM)
#define WT_WOUT (2 * CDIM * DIM + DIM * DIM)

// ---------------- helpers ----------------
__device__ __forceinline__ void mma16(float* c, const uint32_t* a, const uint32_t* b) {
    asm volatile(
        "mma.sync.aligned.m16n8k16.row.col.f32.f16.f16.f32 "
        "{%0,%1,%2,%3},{%4,%5,%6,%7},{%8,%9},{%0,%1,%2,%3};"
        : "+f"(c[0]), "+f"(c[1]), "+f"(c[2]), "+f"(c[3])
        : "r"(a[0]), "r"(a[1]), "r"(a[2]), "r"(a[3]), "r"(b[0]), "r"(b[1]));
}

__device__ __forceinline__ void cpa16(void* dst, const void* src) {
    uint32_t d = (uint32_t)__cvta_generic_to_shared(dst);
    asm volatile("cp.async.cg.shared.global [%0], [%1], 16;" :: "r"(d), "l"(src));
}
__device__ __forceinline__ void cp_commit() { asm volatile("cp.async.commit_group;"); }
template <int NN>
__device__ __forceinline__ void cp_wait() { asm volatile("cp.async.wait_group %0;" :: "n"(NN)); }

__device__ __forceinline__ uint32_t ldh2(const __half* p) {
    return *(const uint32_t*)p;
}
__device__ __forceinline__ uint32_t packh2(float lo, float hi) {
    __half2 h = __floats2half2_rn(lo, hi);
    return *(uint32_t*)&h;
}

// ---------------- fp16 convert kernels ----------------
__global__ __launch_bounds__(256) void cvt_h_kernel(
    const float* __restrict__ src, __half* __restrict__ dst, int n)
{
    int i = blockIdx.x * blockDim.x + threadIdx.x;
    int stride = gridDim.x * blockDim.x;
    for (; i < n; i += stride) dst[i] = __float2half_rn(src[i]);
}

// transpose + fp16: dst[n][k] = h(src[k][n])
__global__ __launch_bounds__(256) void cvt_t_kernel(
    const float* __restrict__ src, __half* __restrict__ dst, int Kd, int Nd)
{
    __shared__ float t[32][33];
    int k0 = blockIdx.x * 32, n0 = blockIdx.y * 32;
    int tx = threadIdx.x & 31, ty = threadIdx.x >> 5;
#pragma unroll
    for (int i = ty; i < 32; i += 8)
        t[i][tx] = src[(size_t)(k0 + i) * Nd + n0 + tx];
    __syncthreads();
#pragma unroll
    for (int i = ty; i < 32; i += 8)
        dst[(size_t)(n0 + i) * Kd + k0 + tx] = __float2half_rn(t[tx][i]);
}

// ---------------- LayerNorm: one warp per row; writes fp32 + fp16 copies ----------------
__global__ __launch_bounds__(256) void ln_kernel(
    const float* __restrict__ x, const float* __restrict__ g,
    const float* __restrict__ b, float* __restrict__ out,
    __half* __restrict__ out_h)
{
    int row = blockIdx.x * 8 + (threadIdx.x >> 5);
    int lane = threadIdx.x & 31;
    const float4* xp = (const float4*)(x + (size_t)row * DIM);
    float4 v[4];
    float s = 0.f;
#pragma unroll
    for (int j = 0; j < 4; j++) {
        v[j] = xp[lane + j * 32];
        s += v[j].x + v[j].y + v[j].z + v[j].w;
    }
#pragma unroll
    for (int o = 16; o; o >>= 1) s += __shfl_xor_sync(0xffffffffu, s, o);
    float mu = s * (1.f / DIM);
    float s2 = 0.f;
#pragma unroll
    for (int j = 0; j < 4; j++) {
        float dx;
        dx = v[j].x - mu; s2 += dx * dx;
        dx = v[j].y - mu; s2 += dx * dx;
        dx = v[j].z - mu; s2 += dx * dx;
        dx = v[j].w - mu; s2 += dx * dx;
    }
#pragma unroll
    for (int o = 16; o; o >>= 1) s2 += __shfl_xor_sync(0xffffffffu, s2, o);
    float rstd = rsqrtf(s2 * (1.f / DIM) + 1e-5f);
    const float4* gp = (const float4*)g;
    const float4* bp = (const float4*)b;
    float4* op = (float4*)(out + (size_t)row * DIM);
    __half2* ohp = (__half2*)(out_h + (size_t)row * DIM);
#pragma unroll
    for (int j = 0; j < 4; j++) {
        int idx = lane + j * 32;
        float4 gg = gp[idx], bb = bp[idx], o;
        o.x = (v[j].x - mu) * rstd * gg.x + bb.x;
        o.y = (v[j].y - mu) * rstd * gg.y + bb.y;
        o.z = (v[j].z - mu) * rstd * gg.z + bb.z;
        o.w = (v[j].w - mu) * rstd * gg.w + bb.w;
        op[idx] = o;
        ohp[idx * 2]     = __floats2half2_rn(o.x, o.y);
        ohp[idx * 2 + 1] = __floats2half2_rn(o.z, o.w);
    }
}

// ---------------- fp16 GEMM (cp.async double-buffered, 64x64 warp tiles) -----------
// out = A[M,K] @ Bt[N,K]^T + bias (+resid). A, Bt fp16 K-major.
// Block 128x128, 128 threads, 4 warps (2m x 2n), ktile 32 halves (2 ksteps of 16).
// outh != null -> write fp16; else write fp32 to outf (with resid).
__global__ __launch_bounds__(128, 2) void gemm_h(
    const __half* __restrict__ A, const __half* __restrict__ Bt,
    const float* __restrict__ bias, const float* __restrict__ resid,
    __half* __restrict__ outh, float* __restrict__ outf, int K, int Nc)
{
    __shared__ __half As[2][128][40];
    __shared__ __half Bs[2][128][40];
    const int tid = threadIdx.x;
    const int w = tid >> 5, lane = tid & 31, grp = lane >> 2, tq = lane & 3;
    const int wm = (w & 1) * 64, wn = (w >> 1) * 64;
    const int m0 = blockIdx.y * 128, n0 = blockIdx.x * 128;

    float acc[4][8][4];
#pragma unroll
    for (int i = 0; i < 4; i++)
#pragma unroll
        for (int j = 0; j < 8; j++)
#pragma unroll
            for (int r = 0; r < 4; r++) acc[i][j][r] = 0.f;

    auto load_tile = [&](int buf, int k0) {
#pragma unroll
        for (int j = 0; j < 4; j++) {
            int lin = tid + j * 128;
            int row = lin >> 2, seg = lin & 3;
            cpa16(&As[buf][row][seg * 8], A + (size_t)(m0 + row) * K + k0 + seg * 8);
        }
#pragma unroll
        for (int j = 0; j < 4; j++) {
            int lin = tid + j * 128;
            int row = lin >> 2, seg = lin & 3;
            cpa16(&Bs[buf][row][seg * 8], Bt + (size_t)(n0 + row) * K + k0 + seg * 8);
        }
    };

    load_tile(0, 0);
    cp_commit();
    load_tile(1, 32);
    cp_commit();

    const int KT = K / 32;
    for (int kt = 0; kt < KT; kt++) {
        cp_wait<1>();
        __syncthreads();
        const int buf = kt & 1;
#pragma unroll
        for (int ks = 0; ks < 2; ks++) {
            uint32_t a[4][4], b[8][2];
#pragma unroll
            for (int mf = 0; mf < 4; mf++) {
                const __half* a0 = &As[buf][wm + mf * 16 + grp][ks * 16];
                const __half* a1 = &As[buf][wm + mf * 16 + grp + 8][ks * 16];
                a[mf][0] = ldh2(a0 + 2 * tq);
                a[mf][1] = ldh2(a1 + 2 * tq);
                a[mf][2] = ldh2(a0 + 8 + 2 * tq);
                a[mf][3] = ldh2(a1 + 8 + 2 * tq);
            }
#pragma unroll
            for (int nf = 0; nf < 8; nf++) {
                const __half* br = &Bs[buf][wn + nf * 8 + grp][ks * 16];
                b[nf][0] = ldh2(br + 2 * tq);
                b[nf][1] = ldh2(br + 8 + 2 * tq);
            }
#pragma unroll
            for (int mf = 0; mf < 4; mf++)
#pragma unroll
                for (int nf = 0; nf < 8; nf++)
                    mma16(acc[mf][nf], a[mf], b[nf]);
        }
        __syncthreads();
        if (kt + 2 < KT) load_tile(buf, (kt + 2) * 32);
        cp_commit();
    }

    // epilogue
#pragma unroll
    for (int mf = 0; mf < 4; mf++) {
        int r = m0 + wm + mf * 16 + grp;
#pragma unroll
        for (int nf = 0; nf < 8; nf++) {
            int c = n0 + wn + nf * 8 + tq * 2;
            float b0 = bias[c], b1 = bias[c + 1];
            float v0 = acc[mf][nf][0] + b0, v1 = acc[mf][nf][1] + b1;
            float v2 = acc[mf][nf][2] + b0, v3 = acc[mf][nf][3] + b1;
            if (outh) {
                *(__half2*)&outh[(size_t)r * Nc + c]       = __floats2half2_rn(v0, v1);
                *(__half2*)&outh[(size_t)(r + 8) * Nc + c] = __floats2half2_rn(v2, v3);
            } else {
                const float* r0p = resid + (size_t)r * Nc + c;
                const float* r1p = resid + (size_t)(r + 8) * Nc + c;
                v0 += r0p[0]; v1 += r0p[1];
                v2 += r1p[0]; v3 += r1p[1];
                *(float2*)&outf[(size_t)r * Nc + c]       = make_float2(v0, v1);
                *(float2*)&outf[(size_t)(r + 8) * Nc + c] = make_float2(v2, v3);
            }
        }
    }
}

// ---------------- fused attention (fp16): 128-query tile, register softmax ----------
// Warp owns 16 q-rows x 256 ctx. S in registers; P pairs ARE the fp16 A-fragments
// (zero shuffles). V transposed in smem so P@V B-frags are aligned half2 loads.
extern __shared__ __half att_sm[];
__global__ __launch_bounds__(256, 1) void attn_kernel(
    const __half* __restrict__ Q, const __half* __restrict__ Kg,
    const __half* __restrict__ Vg, __half* __restrict__ O)
{
    __half* Qs = att_sm;               // [128][72]
    __half* Ks = att_sm + 128 * 72;    // [256][72]
    __half* Vt = Ks + 256 * 72;        // [64][264]  (V transposed: [hd][ctx])

    int b = blockIdx.z, h = blockIdx.y, qt = blockIdx.x;
    int tid = threadIdx.x, w = tid >> 5, lane = tid & 31, grp = lane >> 2, tq = lane & 3;
    size_t qbase = ((size_t)(b * NB + qt * 128)) * DIM + h * HD;
    size_t kbase = ((size_t)(b * MCTX)) * DIM + h * HD;

    // Q, K via cp.async (8-half segments)
#pragma unroll
    for (int j = 0; j < 4; j++) {
        int lin = tid + j * 256;
        int m = lin >> 3, seg = lin & 7;
        cpa16(Qs + m * 72 + seg * 8, Q + qbase + (size_t)m * DIM + seg * 8);
    }
#pragma unroll
    for (int j = 0; j < 8; j++) {
        int lin = tid + j * 256;
        int m = lin >> 3, seg = lin & 7;
        cpa16(Ks + m * 72 + seg * 8, Kg + kbase + (size_t)m * DIM + seg * 8);
    }
    cp_commit();
    // V transposed store (plain loads)
#pragma unroll
    for (int j = 0; j < 32; j++) {
        int idx = tid + j * 256;
        int m = idx & 255, cp = idx >> 8;
        __half2 hv = *(const __half2*)(Vg + kbase + (size_t)m * DIM + cp * 2);
        Vt[(2 * cp) * 264 + m]     = __low2half(hv);
        Vt[(2 * cp + 1) * 264 + m] = __high2half(hv);
    }
    cp_wait<0>();
    __syncthreads();

    const int r0 = w * 16;

    // ---- S = Q @ K^T : p[f][r] covers rows r0+grp(+8), cols f*8+tq*2+{0,1}
    float p[32][4];
#pragma unroll
    for (int f = 0; f < 32; f++)
#pragma unroll
        for (int r = 0; r < 4; r++) p[f][r] = 0.f;

#pragma unroll
    for (int ks = 0; ks < 4; ks++) {
        uint32_t a[4];
        const __half* q0 = Qs + (r0 + grp) * 72 + ks * 16;
        const __half* q1 = Qs + (r0 + grp + 8) * 72 + ks * 16;
        a[0] = ldh2(q0 + 2 * tq);
        a[1] = ldh2(q1 + 2 * tq);
        a[2] = ldh2(q0 + 8 + 2 * tq);
        a[3] = ldh2(q1 + 8 + 2 * tq);
#pragma unroll
        for (int f = 0; f < 32; f++) {
            uint32_t bb[2];
            const __half* kr = Ks + (f * 8 + grp) * 72 + ks * 16;
            bb[0] = ldh2(kr + 2 * tq);
            bb[1] = ldh2(kr + 8 + 2 * tq);
            mma16(p[f], a, bb);
        }
    }

    // ---- softmax in registers (scale folded into exp; row reduce in quad)
    float mxA = -1e30f, mxB = -1e30f;
#pragma unroll
    for (int f = 0; f < 32; f++) {
        mxA = fmaxf(mxA, fmaxf(p[f][0], p[f][1]));
        mxB = fmaxf(mxB, fmaxf(p[f][2], p[f][3]));
    }
    mxA = fmaxf(mxA, __shfl_xor_sync(0xffffffffu, mxA, 1));
    mxA = fmaxf(mxA, __shfl_xor_sync(0xffffffffu, mxA, 2));
    mxB = fmaxf(mxB, __shfl_xor_sync(0xffffffffu, mxB, 1));
    mxB = fmaxf(mxB, __shfl_xor_sync(0xffffffffu, mxB, 2));
    float sA = 0.f, sB = 0.f;
#pragma unroll
    for (int f = 0; f < 32; f++) {
        p[f][0] = __expf(ATT_SCALE * (p[f][0] - mxA)); sA += p[f][0];
        p[f][1] = __expf(ATT_SCALE * (p[f][1] - mxA)); sA += p[f][1];
        p[f][2] = __expf(ATT_SCALE * (p[f][2] - mxB)); sB += p[f][2];
        p[f][3] = __expf(ATT_SCALE * (p[f][3] - mxB)); sB += p[f][3];
    }
    sA += __shfl_xor_sync(0xffffffffu, sA, 1);
    sA += __shfl_xor_sync(0xffffffffu, sA, 2);
    sB += __shfl_xor_sync(0xffffffffu, sB, 1);
    sB += __shfl_xor_sync(0xffffffffu, sB, 2);
    float iA = 1.f / sA, iB = 1.f / sB;

    // ---- pack P to fp16 A-fragments (C-frag layout == A-frag layout for k16)
    uint32_t ph[32][2];
#pragma unroll
    for (int f = 0; f < 32; f++) {
        ph[f][0] = packh2(p[f][0] * iA, p[f][1] * iA);
        ph[f][1] = packh2(p[f][2] * iB, p[f][3] * iB);
    }

    // ---- O = P @ V
    float o[8][4];
#pragma unroll
    for (int f = 0; f < 8; f++)
#pragma unroll
        for (int r = 0; r < 4; r++) o[f][r] = 0.f;

#pragma unroll
    for (int kt = 0; kt < 16; kt++) {
        uint32_t a[4];
        a[0] = ph[2 * kt][0];
        a[1] = ph[2 * kt][1];
        a[2] = ph[2 * kt + 1][0];
        a[3] = ph[2 * kt + 1][1];
#pragma unroll
        for (int f2 = 0; f2 < 8; f2++) {
            uint32_t bb[2];
            const __half* vr = Vt + (f2 * 8 + grp) * 264 + kt * 16;
            bb[0] = ldh2(vr + 2 * tq);
            bb[1] = ldh2(vr + 8 + 2 * tq);
            mma16(o[f2], a, bb);
        }
    }

    // epilogue: fp16 attention output
#pragma unroll
    for (int f2 = 0; f2 < 8; f2++) {
        int col = f2 * 8 + tq * 2;
        *(__half2*)&O[qbase + (size_t)(r0 + grp) * DIM + col] =
            __floats2half2_rn(o[f2][0], o[f2][1]);
        *(__half2*)&O[qbase + (size_t)(r0 + grp + 8) * DIM + col] =
            __floats2half2_rn(o[f2][2], o[f2][3]);
    }
}

// ---------------- launcher ----------------
extern "C" void kernel_launch(void* const* d_in, const int* in_sizes, int n_in,
                              void* d_out, int out_size)
{
    const float* features = (const float*)d_in[0];
    // d_in[1] = batch_indices: sorted, equal counts -> batch = row / NB (arithmetic)
    const float* context = (const float*)d_in[2];
    const float* Wq = (const float*)d_in[3];
    const float* bq = (const float*)d_in[4];
    const float* Wk = (const float*)d_in[5];
    const float* bk = (const float*)d_in[6];
    const float* Wv = (const float*)d_in[7];
    const float* bv = (const float*)d_in[8];
    const float* Wout = (const float*)d_in[9];
    const float* bout = (const float*)d_in[10];
    const float* ln_g = (const float*)d_in[11];
    const float* ln_b = (const float*)d_in[12];
    float* out = (float*)d_out;

    float* f_p;
    __half *fh_p, *q_p, *k_p, *v_p, *att_p, *ctx_p, *wt_p;
    cudaGetSymbolAddress((void**)&f_p, g_f);
    cudaGetSymbolAddress((void**)&fh_p, g_fh);
    cudaGetSymbolAddress((void**)&q_p, g_q);
    cudaGetSymbolAddress((void**)&k_p, g_k);
    cudaGetSymbolAddress((void**)&v_p, g_v);
    cudaGetSymbolAddress((void**)&att_p, g_att);
    cudaGetSymbolAddress((void**)&ctx_p, g_ctx);
    cudaGetSymbolAddress((void**)&wt_p, g_wt);

    cudaFuncSetAttribute(attn_kernel, cudaFuncAttributeMaxDynamicSharedMemorySize, 89088);

    // fp16 conversions: context; weights transposed to K-major [N][K]
    cvt_h_kernel<<<2048, 256>>>(context, ctx_p, BATCH * MCTX * CDIM);
    cvt_t_kernel<<<dim3(CDIM / 32, DIM / 32), 256>>>(Wk, wt_p + WT_WK, CDIM, DIM);
    cvt_t_kernel<<<dim3(CDIM / 32, DIM / 32), 256>>>(Wv, wt_p + WT_WV, CDIM, DIM);
    cvt_t_kernel<<<dim3(DIM / 32, DIM / 32), 256>>>(Wq, wt_p + WT_WQ, DIM, DIM);
    cvt_t_kernel<<<dim3(DIM / 32, DIM / 32), 256>>>(Wout, wt_p + WT_WOUT, DIM, DIM);

    // 1. LayerNorm (fp32 + fp16 outputs)
    ln_kernel<<<N_TOK / 8, 256>>>(features, ln_g, ln_b, f_p, fh_p);
    // 2. K, V projections: (2048, 768) @ (768, 512)
    gemm_h<<<dim3(DIM / 128, (BATCH * MCTX) / 128), 128>>>(
        ctx_p, wt_p + WT_WK, bk, nullptr, k_p, nullptr, CDIM, DIM);
    gemm_h<<<dim3(DIM / 128, (BATCH * MCTX) / 128), 128>>>(
        ctx_p, wt_p + WT_WV, bv, nullptr, v_p, nullptr, CDIM, DIM);
    // 3. Q projection: (131072, 512) @ (512, 512)
    gemm_h<<<dim3(DIM / 128, N_TOK / 128), 128>>>(
        fh_p, wt_p + WT_WQ, bq, nullptr, q_p, nullptr, DIM, DIM);
    // 4. Attention
    attn_kernel<<<dim3(NB / 128, NH, BATCH), 256, 89088>>>(q_p, k_p, v_p, att_p);
    // 5. Output projection + bias + residual (fp32 out)
    gemm_h<<<dim3(DIM / 128, N_TOK / 128), 128>>>(
        att_p, wt_p + WT_WOUT, bout, f_p, nullptr, out, DIM, DIM);
}

// round 11
// speedup vs baseline: 2.1157x; 1.0425x over previous
#include <cuda_runtime.h>
#include <cuda_fp16.h>
#include <cstdint>

#define N_TOK 131072
#define BATCH 8
#define MCTX 256
#define DIM 512
#define CDIM 768
#define NH 8
#define HD 64
#define NB (N_TOK / BATCH)
#define ATT_SCALE 0.125f

// ---------------- scratch (device globals; no runtime allocation) ----------------
__device__ float  g_f[(size_t)N_TOK * DIM];      // LayerNorm output fp32 (residual)
__device__ __half g_fh[(size_t)N_TOK * DIM];     // LayerNorm output fp16
__device__ __half g_q[(size_t)N_TOK * DIM];      // Q projection fp16
__device__ __half g_k[BATCH * MCTX * DIM];       // K projection fp16
__device__ __half g_v[BATCH * MCTX * DIM];       // V projection fp16
__device__ __half g_att[(size_t)N_TOK * DIM];    // attention out fp16
__device__ __half g_ctx[BATCH * MCTX * CDIM];    // context fp16
__device__ __half g_wt[2 * CDIM * DIM + 2 * DIM * DIM]; // WkT,WvT,WqT,WoutT fp16, K-major [N][K]

#define WT_WK 0
#define WT_WV (CDIM * DIM)
#define WT_WQ (2 * CDIM * DIM)
#define WT_WOUT (2 * CDIM * DIM + DIM * DIM)

// ---------------- helpers ----------------
__device__ __forceinline__ void mma16(float* c, const uint32_t* a, const uint32_t* b) {
    asm volatile(
        "mma.sync.aligned.m16n8k16.row.col.f32.f16.f16.f32 "
        "{%0,%1,%2,%3},{%4,%5,%6,%7},{%8,%9},{%0,%1,%2,%3};"
        : "+f"(c[0]), "+f"(c[1]), "+f"(c[2]), "+f"(c[3])
        : "r"(a[0]), "r"(a[1]), "r"(a[2]), "r"(a[3]), "r"(b[0]), "r"(b[1]));
}

__device__ __forceinline__ void ldsm4(uint32_t* r, const __half* p) {
    uint32_t a = (uint32_t)__cvta_generic_to_shared(p);
    asm volatile("ldmatrix.sync.aligned.m8n8.x4.shared.b16 {%0,%1,%2,%3}, [%4];"
        : "=r"(r[0]), "=r"(r[1]), "=r"(r[2]), "=r"(r[3]) : "r"(a));
}

__device__ __forceinline__ void cpa16(void* dst, const void* src) {
    uint32_t d = (uint32_t)__cvta_generic_to_shared(dst);
    asm volatile("cp.async.cg.shared.global [%0], [%1], 16;" :: "r"(d), "l"(src));
}
__device__ __forceinline__ void cp_commit() { asm volatile("cp.async.commit_group;"); }
template <int NN>
__device__ __forceinline__ void cp_wait() { asm volatile("cp.async.wait_group %0;" :: "n"(NN)); }

__device__ __forceinline__ uint32_t packh2(float lo, float hi) {
    __half2 h = __floats2half2_rn(lo, hi);
    return *(uint32_t*)&h;
}

// ---------------- fp16 convert kernels ----------------
__global__ __launch_bounds__(256) void cvt_h_kernel(
    const float* __restrict__ src, __half* __restrict__ dst, int n)
{
    int i = blockIdx.x * blockDim.x + threadIdx.x;
    int stride = gridDim.x * blockDim.x;
    for (; i < n; i += stride) dst[i] = __float2half_rn(src[i]);
}

// transpose + fp16: dst[n][k] = h(src[k][n])
__global__ __launch_bounds__(256) void cvt_t_kernel(
    const float* __restrict__ src, __half* __restrict__ dst, int Kd, int Nd)
{
    __shared__ float t[32][33];
    int k0 = blockIdx.x * 32, n0 = blockIdx.y * 32;
    int tx = threadIdx.x & 31, ty = threadIdx.x >> 5;
#pragma unroll
    for (int i = ty; i < 32; i += 8)
        t[i][tx] = src[(size_t)(k0 + i) * Nd + n0 + tx];
    __syncthreads();
#pragma unroll
    for (int i = ty; i < 32; i += 8)
        dst[(size_t)(n0 + i) * Kd + k0 + tx] = __float2half_rn(t[tx][i]);
}

// ---------------- LayerNorm: one warp per row; writes fp32 + fp16 copies ----------------
__global__ __launch_bounds__(256) void ln_kernel(
    const float* __restrict__ x, const float* __restrict__ g,
    const float* __restrict__ b, float* __restrict__ out,
    __half* __restrict__ out_h)
{
    int row = blockIdx.x * 8 + (threadIdx.x >> 5);
    int lane = threadIdx.x & 31;
    const float4* xp = (const float4*)(x + (size_t)row * DIM);
    float4 v[4];
    float s = 0.f;
#pragma unroll
    for (int j = 0; j < 4; j++) {
        v[j] = xp[lane + j * 32];
        s += v[j].x + v[j].y + v[j].z + v[j].w;
    }
#pragma unroll
    for (int o = 16; o; o >>= 1) s += __shfl_xor_sync(0xffffffffu, s, o);
    float mu = s * (1.f / DIM);
    float s2 = 0.f;
#pragma unroll
    for (int j = 0; j < 4; j++) {
        float dx;
        dx = v[j].x - mu; s2 += dx * dx;
        dx = v[j].y - mu; s2 += dx * dx;
        dx = v[j].z - mu; s2 += dx * dx;
        dx = v[j].w - mu; s2 += dx * dx;
    }
#pragma unroll
    for (int o = 16; o; o >>= 1) s2 += __shfl_xor_sync(0xffffffffu, s2, o);
    float rstd = rsqrtf(s2 * (1.f / DIM) + 1e-5f);
    const float4* gp = (const float4*)g;
    const float4* bp = (const float4*)b;
    float4* op = (float4*)(out + (size_t)row * DIM);
    __half2* ohp = (__half2*)(out_h + (size_t)row * DIM);
#pragma unroll
    for (int j = 0; j < 4; j++) {
        int idx = lane + j * 32;
        float4 gg = gp[idx], bb = bp[idx], o;
        o.x = (v[j].x - mu) * rstd * gg.x + bb.x;
        o.y = (v[j].y - mu) * rstd * gg.y + bb.y;
        o.z = (v[j].z - mu) * rstd * gg.z + bb.z;
        o.w = (v[j].w - mu) * rstd * gg.w + bb.w;
        op[idx] = o;
        ohp[idx * 2]     = __floats2half2_rn(o.x, o.y);
        ohp[idx * 2 + 1] = __floats2half2_rn(o.z, o.w);
    }
}

// ---------------- fp16 GEMM (cp.async double-buffered, ldmatrix, 64x64 warp tiles) --
// out = A[M,K] @ Bt[N,K]^T + bias (+resid). A, Bt fp16 K-major.
// Block 128x128, 128 threads, 4 warps (2m x 2n), ktile 32 halves (2 ksteps of 16).
__global__ __launch_bounds__(128, 2) void gemm_h(
    const __half* __restrict__ A, const __half* __restrict__ Bt,
    const float* __restrict__ bias, const float* __restrict__ resid,
    __half* __restrict__ outh, float* __restrict__ outf, int K, int Nc)
{
    __shared__ __half As[2][128][40];
    __shared__ __half Bs[2][128][40];
    const int tid = threadIdx.x;
    const int w = tid >> 5, lane = tid & 31, grp = lane >> 2, tq = lane & 3;
    const int wm = (w & 1) * 64, wn = (w >> 1) * 64;
    const int m0 = blockIdx.y * 128, n0 = blockIdx.x * 128;
    const int lr = lane & 7, sect = lane >> 3;   // ldmatrix addressing
    const int sa_row = (sect & 1) * 8 + lr, sa_col = (sect >> 1) * 8;
    const int sb_row = (sect >> 1) * 8 + lr, sb_col = (sect & 1) * 8;

    float acc[4][8][4];
#pragma unroll
    for (int i = 0; i < 4; i++)
#pragma unroll
        for (int j = 0; j < 8; j++)
#pragma unroll
            for (int r = 0; r < 4; r++) acc[i][j][r] = 0.f;

    auto load_tile = [&](int buf, int k0) {
#pragma unroll
        for (int j = 0; j < 4; j++) {
            int lin = tid + j * 128;
            int row = lin >> 2, seg = lin & 3;
            cpa16(&As[buf][row][seg * 8], A + (size_t)(m0 + row) * K + k0 + seg * 8);
        }
#pragma unroll
        for (int j = 0; j < 4; j++) {
            int lin = tid + j * 128;
            int row = lin >> 2, seg = lin & 3;
            cpa16(&Bs[buf][row][seg * 8], Bt + (size_t)(n0 + row) * K + k0 + seg * 8);
        }
    };

    load_tile(0, 0);
    cp_commit();
    load_tile(1, 32);
    cp_commit();

    const int KT = K / 32;
    for (int kt = 0; kt < KT; kt++) {
        cp_wait<1>();
        __syncthreads();
        const int buf = kt & 1;
#pragma unroll
        for (int ks = 0; ks < 2; ks++) {
            uint32_t a[4][4], b[8][2];
#pragma unroll
            for (int mf = 0; mf < 4; mf++)
                ldsm4(a[mf], &As[buf][wm + mf * 16 + sa_row][ks * 16 + sa_col]);
#pragma unroll
            for (int nf2 = 0; nf2 < 4; nf2++) {
                uint32_t t[4];
                ldsm4(t, &Bs[buf][wn + nf2 * 16 + sb_row][ks * 16 + sb_col]);
                b[2 * nf2][0] = t[0]; b[2 * nf2][1] = t[1];
                b[2 * nf2 + 1][0] = t[2]; b[2 * nf2 + 1][1] = t[3];
            }
#pragma unroll
            for (int mf = 0; mf < 4; mf++)
#pragma unroll
                for (int nf = 0; nf < 8; nf++)
                    mma16(acc[mf][nf], a[mf], b[nf]);
        }
        __syncthreads();
        if (kt + 2 < KT) load_tile(buf, (kt + 2) * 32);
        cp_commit();
    }

    // epilogue
#pragma unroll
    for (int mf = 0; mf < 4; mf++) {
        int r = m0 + wm + mf * 16 + grp;
#pragma unroll
        for (int nf = 0; nf < 8; nf++) {
            int c = n0 + wn + nf * 8 + tq * 2;
            float b0 = bias[c], b1 = bias[c + 1];
            float v0 = acc[mf][nf][0] + b0, v1 = acc[mf][nf][1] + b1;
            float v2 = acc[mf][nf][2] + b0, v3 = acc[mf][nf][3] + b1;
            if (outh) {
                *(__half2*)&outh[(size_t)r * Nc + c]       = __floats2half2_rn(v0, v1);
                *(__half2*)&outh[(size_t)(r + 8) * Nc + c] = __floats2half2_rn(v2, v3);
            } else {
                const float* r0p = resid + (size_t)r * Nc + c;
                const float* r1p = resid + (size_t)(r + 8) * Nc + c;
                v0 += r0p[0]; v1 += r0p[1];
                v2 += r1p[0]; v3 += r1p[1];
                *(float2*)&outf[(size_t)r * Nc + c]       = make_float2(v0, v1);
                *(float2*)&outf[(size_t)(r + 8) * Nc + c] = make_float2(v2, v3);
            }
        }
    }
}

// ---------------- fused attention (fp16): 128-query tile, register softmax ----------
// Warp owns 16 q-rows x 256 ctx. S in registers; P pairs ARE the fp16 A-fragments.
// All fragment loads via ldmatrix.x4.
extern __shared__ __half att_sm[];
__global__ __launch_bounds__(256, 1) void attn_kernel(
    const __half* __restrict__ Q, const __half* __restrict__ Kg,
    const __half* __restrict__ Vg, __half* __restrict__ O)
{
    __half* Qs = att_sm;               // [128][72]
    __half* Ks = att_sm + 128 * 72;    // [256][72]
    __half* Vt = Ks + 256 * 72;        // [64][264]  (V transposed: [hd][ctx])

    int b = blockIdx.z, h = blockIdx.y, qt = blockIdx.x;
    int tid = threadIdx.x, w = tid >> 5, lane = tid & 31, grp = lane >> 2, tq = lane & 3;
    const int lr = lane & 7, sect = lane >> 3;
    const int sa_row = (sect & 1) * 8 + lr, sa_col = (sect >> 1) * 8;
    const int sb_row = (sect >> 1) * 8 + lr, sb_col = (sect & 1) * 8;
    size_t qbase = ((size_t)(b * NB + qt * 128)) * DIM + h * HD;
    size_t kbase = ((size_t)(b * MCTX)) * DIM + h * HD;

    // Q, K via cp.async (8-half segments)
#pragma unroll
    for (int j = 0; j < 4; j++) {
        int lin = tid + j * 256;
        int m = lin >> 3, seg = lin & 7;
        cpa16(Qs + m * 72 + seg * 8, Q + qbase + (size_t)m * DIM + seg * 8);
    }
#pragma unroll
    for (int j = 0; j < 8; j++) {
        int lin = tid + j * 256;
        int m = lin >> 3, seg = lin & 7;
        cpa16(Ks + m * 72 + seg * 8, Kg + kbase + (size_t)m * DIM + seg * 8);
    }
    cp_commit();
    // V transposed store (plain loads)
#pragma unroll
    for (int j = 0; j < 32; j++) {
        int idx = tid + j * 256;
        int m = idx & 255, cp = idx >> 8;
        __half2 hv = *(const __half2*)(Vg + kbase + (size_t)m * DIM + cp * 2);
        Vt[(2 * cp) * 264 + m]     = __low2half(hv);
        Vt[(2 * cp + 1) * 264 + m] = __high2half(hv);
    }
    cp_wait<0>();
    __syncthreads();

    const int r0 = w * 16;

    // ---- S = Q @ K^T : p[f][r] covers rows r0+grp(+8), cols f*8+tq*2+{0,1}
    float p[32][4];
#pragma unroll
    for (int f = 0; f < 32; f++)
#pragma unroll
        for (int r = 0; r < 4; r++) p[f][r] = 0.f;

#pragma unroll
    for (int ks = 0; ks < 4; ks++) {
        uint32_t a[4];
        ldsm4(a, Qs + (r0 + sa_row) * 72 + ks * 16 + sa_col);
#pragma unroll
        for (int fp = 0; fp < 16; fp++) {
            uint32_t t[4];
            ldsm4(t, Ks + (fp * 16 + sb_row) * 72 + ks * 16 + sb_col);
            mma16(p[2 * fp], a, t);
            mma16(p[2 * fp + 1], a, t + 2);
        }
    }

    // ---- softmax in registers (scale folded into exp; row reduce in quad)
    float mxA = -1e30f, mxB = -1e30f;
#pragma unroll
    for (int f = 0; f < 32; f++) {
        mxA = fmaxf(mxA, fmaxf(p[f][0], p[f][1]));
        mxB = fmaxf(mxB, fmaxf(p[f][2], p[f][3]));
    }
    mxA = fmaxf(mxA, __shfl_xor_sync(0xffffffffu, mxA, 1));
    mxA = fmaxf(mxA, __shfl_xor_sync(0xffffffffu, mxA, 2));
    mxB = fmaxf(mxB, __shfl_xor_sync(0xffffffffu, mxB, 1));
    mxB = fmaxf(mxB, __shfl_xor_sync(0xffffffffu, mxB, 2));
    float sA = 0.f, sB = 0.f;
#pragma unroll
    for (int f = 0; f < 32; f++) {
        p[f][0] = __expf(ATT_SCALE * (p[f][0] - mxA)); sA += p[f][0];
        p[f][1] = __expf(ATT_SCALE * (p[f][1] - mxA)); sA += p[f][1];
        p[f][2] = __expf(ATT_SCALE * (p[f][2] - mxB)); sB += p[f][2];
        p[f][3] = __expf(ATT_SCALE * (p[f][3] - mxB)); sB += p[f][3];
    }
    sA += __shfl_xor_sync(0xffffffffu, sA, 1);
    sA += __shfl_xor_sync(0xffffffffu, sA, 2);
    sB += __shfl_xor_sync(0xffffffffu, sB, 1);
    sB += __shfl_xor_sync(0xffffffffu, sB, 2);
    float iA = 1.f / sA, iB = 1.f / sB;

    // ---- pack P to fp16 A-fragments (C-frag layout == A-frag layout for k16)
    uint32_t ph[32][2];
#pragma unroll
    for (int f = 0; f < 32; f++) {
        ph[f][0] = packh2(p[f][0] * iA, p[f][1] * iA);
        ph[f][1] = packh2(p[f][2] * iB, p[f][3] * iB);
    }

    // ---- O = P @ V (B-frags via ldmatrix from transposed V)
    float o[8][4];
#pragma unroll
    for (int f = 0; f < 8; f++)
#pragma unroll
        for (int r = 0; r < 4; r++) o[f][r] = 0.f;

#pragma unroll
    for (int kt = 0; kt < 16; kt++) {
        uint32_t a[4];
        a[0] = ph[2 * kt][0];
        a[1] = ph[2 * kt][1];
        a[2] = ph[2 * kt + 1][0];
        a[3] = ph[2 * kt + 1][1];
#pragma unroll
        for (int f2p = 0; f2p < 4; f2p++) {
            uint32_t t[4];
            ldsm4(t, Vt + (f2p * 16 + sb_row) * 264 + kt * 16 + sb_col);
            mma16(o[2 * f2p], a, t);
            mma16(o[2 * f2p + 1], a, t + 2);
        }
    }

    // epilogue: fp16 attention output
#pragma unroll
    for (int f2 = 0; f2 < 8; f2++) {
        int col = f2 * 8 + tq * 2;
        *(__half2*)&O[qbase + (size_t)(r0 + grp) * DIM + col] =
            __floats2half2_rn(o[f2][0], o[f2][1]);
        *(__half2*)&O[qbase + (size_t)(r0 + grp + 8) * DIM + col] =
            __floats2half2_rn(o[f2][2], o[f2][3]);
    }
}

// ---------------- launcher ----------------
extern "C" void kernel_launch(void* const* d_in, const int* in_sizes, int n_in,
                              void* d_out, int out_size)
{
    const float* features = (const float*)d_in[0];
    // d_in[1] = batch_indices: sorted, equal counts -> batch = row / NB (arithmetic)
    const float* context = (const float*)d_in[2];
    const float* Wq = (const float*)d_in[3];
    const float* bq = (const float*)d_in[4];
    const float* Wk = (const float*)d_in[5];
    const float* bk = (const float*)d_in[6];
    const float* Wv = (const float*)d_in[7];
    const float* bv = (const float*)d_in[8];
    const float* Wout = (const float*)d_in[9];
    const float* bout = (const float*)d_in[10];
    const float* ln_g = (const float*)d_in[11];
    const float* ln_b = (const float*)d_in[12];
    float* out = (float*)d_out;

    float* f_p;
    __half *fh_p, *q_p, *k_p, *v_p, *att_p, *ctx_p, *wt_p;
    cudaGetSymbolAddress((void**)&f_p, g_f);
    cudaGetSymbolAddress((void**)&fh_p, g_fh);
    cudaGetSymbolAddress((void**)&q_p, g_q);
    cudaGetSymbolAddress((void**)&k_p, g_k);
    cudaGetSymbolAddress((void**)&v_p, g_v);
    cudaGetSymbolAddress((void**)&att_p, g_att);
    cudaGetSymbolAddress((void**)&ctx_p, g_ctx);
    cudaGetSymbolAddress((void**)&wt_p, g_wt);

    cudaFuncSetAttribute(attn_kernel, cudaFuncAttributeMaxDynamicSharedMemorySize, 89088);

    // fp16 conversions: context; weights transposed to K-major [N][K]
    cvt_h_kernel<<<2048, 256>>>(context, ctx_p, BATCH * MCTX * CDIM);
    cvt_t_kernel<<<dim3(CDIM / 32, DIM / 32), 256>>>(Wk, wt_p + WT_WK, CDIM, DIM);
    cvt_t_kernel<<<dim3(CDIM / 32, DIM / 32), 256>>>(Wv, wt_p + WT_WV, CDIM, DIM);
    cvt_t_kernel<<<dim3(DIM / 32, DIM / 32), 256>>>(Wq, wt_p + WT_WQ, DIM, DIM);
    cvt_t_kernel<<<dim3(DIM / 32, DIM / 32), 256>>>(Wout, wt_p + WT_WOUT, DIM, DIM);

    // 1. LayerNorm (fp32 + fp16 outputs)
    ln_kernel<<<N_TOK / 8, 256>>>(features, ln_g, ln_b, f_p, fh_p);
    // 2. K, V projections: (2048, 768) @ (768, 512)
    gemm_h<<<dim3(DIM / 128, (BATCH * MCTX) / 128), 128>>>(
        ctx_p, wt_p + WT_WK, bk, nullptr, k_p, nullptr, CDIM, DIM);
    gemm_h<<<dim3(DIM / 128, (BATCH * MCTX) / 128), 128>>>(
        ctx_p, wt_p + WT_WV, bv, nullptr, v_p, nullptr, CDIM, DIM);
    // 3. Q projection: (131072, 512) @ (512, 512)
    gemm_h<<<dim3(DIM / 128, N_TOK / 128), 128>>>(
        fh_p, wt_p + WT_WQ, bq, nullptr, q_p, nullptr, DIM, DIM);
    // 4. Attention
    attn_kernel<<<dim3(NB / 128, NH, BATCH), 256, 89088>>>(q_p, k_p, v_p, att_p);
    // 5. Output projection + bias + residual (fp32 out)
    gemm_h<<<dim3(DIM / 128, N_TOK / 128), 128>>>(
        att_p, wt_p + WT_WOUT, bout, f_p, nullptr, out, DIM, DIM);
}

// round 12
// speedup vs baseline: 2.3120x; 1.0928x over previous
#include <cuda_runtime.h>
#include <cuda_fp16.h>
#include <cstdint>

#define N_TOK 131072
#define BATCH 8
#define MCTX 256
#define DIM 512
#define CDIM 768
#define NH 8
#define HD 64
#define NB (N_TOK / BATCH)
// ATT_SCALE * log2(e) = 0.125 * 1.4426950408889634
#define ATT_C2 0.18033688011112043f

// ---------------- scratch (device globals; no runtime allocation) ----------------
__device__ __half g_fh[(size_t)N_TOK * DIM];     // LayerNorm output fp16 (A for Qproj + residual)
__device__ __half g_q[(size_t)N_TOK * DIM];      // Q projection fp16
__device__ __half g_kv[BATCH * MCTX * 2 * DIM];  // K|V combined: row m, cols [0,512)=K, [512,1024)=V
__device__ __half g_att[(size_t)N_TOK * DIM];    // attention out fp16
__device__ __half g_ctx[BATCH * MCTX * CDIM];    // context fp16
__device__ __half g_wt[2 * CDIM * DIM + 2 * DIM * DIM]; // WkT,WvT,WqT,WoutT fp16, K-major [N][K]
__device__ float  g_bkv[2 * DIM];                // bk || bv

#define WT_WK 0
#define WT_WV (CDIM * DIM)
#define WT_WQ (2 * CDIM * DIM)
#define WT_WOUT (2 * CDIM * DIM + DIM * DIM)

// ---------------- helpers ----------------
__device__ __forceinline__ void mma16(float* c, const uint32_t* a, const uint32_t* b) {
    asm volatile(
        "mma.sync.aligned.m16n8k16.row.col.f32.f16.f16.f32 "
        "{%0,%1,%2,%3},{%4,%5,%6,%7},{%8,%9},{%0,%1,%2,%3};"
        : "+f"(c[0]), "+f"(c[1]), "+f"(c[2]), "+f"(c[3])
        : "r"(a[0]), "r"(a[1]), "r"(a[2]), "r"(a[3]), "r"(b[0]), "r"(b[1]));
}

__device__ __forceinline__ void ldsm4(uint32_t* r, const __half* p) {
    uint32_t a = (uint32_t)__cvta_generic_to_shared(p);
    asm volatile("ldmatrix.sync.aligned.m8n8.x4.shared.b16 {%0,%1,%2,%3}, [%4];"
        : "=r"(r[0]), "=r"(r[1]), "=r"(r[2]), "=r"(r[3]) : "r"(a));
}

__device__ __forceinline__ void cpa16(void* dst, const void* src) {
    uint32_t d = (uint32_t)__cvta_generic_to_shared(dst);
    asm volatile("cp.async.cg.shared.global [%0], [%1], 16;" :: "r"(d), "l"(src));
}
__device__ __forceinline__ void cp_commit() { asm volatile("cp.async.commit_group;"); }
template <int NN>
__device__ __forceinline__ void cp_wait() { asm volatile("cp.async.wait_group %0;" :: "n"(NN)); }

__device__ __forceinline__ uint32_t packh2(float lo, float hi) {
    __half2 h = __floats2half2_rn(lo, hi);
    return *(uint32_t*)&h;
}
__device__ __forceinline__ uint32_t ex2h2(uint32_t x) {
    uint32_t r;
    asm("ex2.approx.f16x2 %0, %1;" : "=r"(r) : "r"(x));
    return r;
}

// ---------------- fp16 convert kernels ----------------
__global__ __launch_bounds__(256) void cvt_h_kernel(
    const float* __restrict__ src, __half* __restrict__ dst, int n)
{
    int i = blockIdx.x * blockDim.x + threadIdx.x;
    int stride = gridDim.x * blockDim.x;
    for (; i < n; i += stride) dst[i] = __float2half_rn(src[i]);
}

// merged transpose + fp16 for the 4 weights: dst[n][k] = h(src[k][n])
__global__ __launch_bounds__(256) void cvt_t4_kernel(
    const float* __restrict__ s0, const float* __restrict__ s1,
    const float* __restrict__ s2, const float* __restrict__ s3,
    __half* __restrict__ wt)
{
    __shared__ float t[32][33];
    int z = blockIdx.z;
    const float* src = (z == 0) ? s0 : (z == 1) ? s1 : (z == 2) ? s2 : s3;
    int Kd = (z < 2) ? CDIM : DIM;
    size_t doff = (z == 0) ? WT_WK : (z == 1) ? WT_WV : (z == 2) ? WT_WQ : (size_t)WT_WOUT;
    int k0 = blockIdx.x * 32, n0 = blockIdx.y * 32;
    if (k0 >= Kd) return;
    __half* dst = wt + doff;
    int tx = threadIdx.x & 31, ty = threadIdx.x >> 5;
#pragma unroll
    for (int i = ty; i < 32; i += 8)
        t[i][tx] = src[(size_t)(k0 + i) * DIM + n0 + tx];
    __syncthreads();
#pragma unroll
    for (int i = ty; i < 32; i += 8)
        dst[(size_t)(n0 + i) * Kd + k0 + tx] = __float2half_rn(t[tx][i]);
}

__global__ void bias_cat_kernel(const float* __restrict__ bk, const float* __restrict__ bv,
                                float* __restrict__ dst)
{
    int i = threadIdx.x + blockIdx.x * blockDim.x;
    if (i < DIM) dst[i] = bk[i];
    else if (i < 2 * DIM) dst[i] = bv[i - DIM];
}

// ---------------- LayerNorm: one warp per row; writes fp16 only ----------------
__global__ __launch_bounds__(256) void ln_kernel(
    const float* __restrict__ x, const float* __restrict__ g,
    const float* __restrict__ b, __half* __restrict__ out_h)
{
    int row = blockIdx.x * 8 + (threadIdx.x >> 5);
    int lane = threadIdx.x & 31;
    const float4* xp = (const float4*)(x + (size_t)row * DIM);
    float4 v[4];
    float s = 0.f;
#pragma unroll
    for (int j = 0; j < 4; j++) {
        v[j] = xp[lane + j * 32];
        s += v[j].x + v[j].y + v[j].z + v[j].w;
    }
#pragma unroll
    for (int o = 16; o; o >>= 1) s += __shfl_xor_sync(0xffffffffu, s, o);
    float mu = s * (1.f / DIM);
    float s2 = 0.f;
#pragma unroll
    for (int j = 0; j < 4; j++) {
        float dx;
        dx = v[j].x - mu; s2 += dx * dx;
        dx = v[j].y - mu; s2 += dx * dx;
        dx = v[j].z - mu; s2 += dx * dx;
        dx = v[j].w - mu; s2 += dx * dx;
    }
#pragma unroll
    for (int o = 16; o; o >>= 1) s2 += __shfl_xor_sync(0xffffffffu, s2, o);
    float rstd = rsqrtf(s2 * (1.f / DIM) + 1e-5f);
    const float4* gp = (const float4*)g;
    const float4* bp = (const float4*)b;
    __half2* ohp = (__half2*)(out_h + (size_t)row * DIM);
#pragma unroll
    for (int j = 0; j < 4; j++) {
        int idx = lane + j * 32;
        float4 gg = gp[idx], bb = bp[idx];
        float ox = (v[j].x - mu) * rstd * gg.x + bb.x;
        float oy = (v[j].y - mu) * rstd * gg.y + bb.y;
        float oz = (v[j].z - mu) * rstd * gg.z + bb.z;
        float ow = (v[j].w - mu) * rstd * gg.w + bb.w;
        ohp[idx * 2]     = __floats2half2_rn(ox, oy);
        ohp[idx * 2 + 1] = __floats2half2_rn(oz, ow);
    }
}

// ---------------- fp16 GEMM (cp.async double-buffered, ldmatrix, 64x64 warp tiles) --
// out = A[M,K] @ Bt[N,K]^T + bias (+fp16 resid). A, Bt fp16 K-major.
__global__ __launch_bounds__(128, 2) void gemm_h(
    const __half* __restrict__ A, const __half* __restrict__ Bt,
    const float* __restrict__ bias, const __half* __restrict__ resid,
    __half* __restrict__ outh, float* __restrict__ outf, int K, int Nc)
{
    __shared__ __half As[2][128][40];
    __shared__ __half Bs[2][128][40];
    const int tid = threadIdx.x;
    const int w = tid >> 5, lane = tid & 31, grp = lane >> 2, tq = lane & 3;
    const int wm = (w & 1) * 64, wn = (w >> 1) * 64;
    const int m0 = blockIdx.y * 128, n0 = blockIdx.x * 128;
    const int lr = lane & 7, sect = lane >> 3;   // ldmatrix addressing
    const int sa_row = (sect & 1) * 8 + lr, sa_col = (sect >> 1) * 8;
    const int sb_row = (sect >> 1) * 8 + lr, sb_col = (sect & 1) * 8;

    float acc[4][8][4];
#pragma unroll
    for (int i = 0; i < 4; i++)
#pragma unroll
        for (int j = 0; j < 8; j++)
#pragma unroll
            for (int r = 0; r < 4; r++) acc[i][j][r] = 0.f;

    auto load_tile = [&](int buf, int k0) {
#pragma unroll
        for (int j = 0; j < 4; j++) {
            int lin = tid + j * 128;
            int row = lin >> 2, seg = lin & 3;
            cpa16(&As[buf][row][seg * 8], A + (size_t)(m0 + row) * K + k0 + seg * 8);
        }
#pragma unroll
        for (int j = 0; j < 4; j++) {
            int lin = tid + j * 128;
            int row = lin >> 2, seg = lin & 3;
            cpa16(&Bs[buf][row][seg * 8], Bt + (size_t)(n0 + row) * K + k0 + seg * 8);
        }
    };

    load_tile(0, 0);
    cp_commit();
    load_tile(1, 32);
    cp_commit();

    const int KT = K / 32;
    for (int kt = 0; kt < KT; kt++) {
        cp_wait<1>();
        __syncthreads();
        const int buf = kt & 1;
#pragma unroll
        for (int ks = 0; ks < 2; ks++) {
            uint32_t a[4][4], b[8][2];
#pragma unroll
            for (int mf = 0; mf < 4; mf++)
                ldsm4(a[mf], &As[buf][wm + mf * 16 + sa_row][ks * 16 + sa_col]);
#pragma unroll
            for (int nf2 = 0; nf2 < 4; nf2++) {
                uint32_t t[4];
                ldsm4(t, &Bs[buf][wn + nf2 * 16 + sb_row][ks * 16 + sb_col]);
                b[2 * nf2][0] = t[0]; b[2 * nf2][1] = t[1];
                b[2 * nf2 + 1][0] = t[2]; b[2 * nf2 + 1][1] = t[3];
            }
#pragma unroll
            for (int mf = 0; mf < 4; mf++)
#pragma unroll
                for (int nf = 0; nf < 8; nf++)
                    mma16(acc[mf][nf], a[mf], b[nf]);
        }
        __syncthreads();
        if (kt + 2 < KT) load_tile(buf, (kt + 2) * 32);
        cp_commit();
    }

    // epilogue
#pragma unroll
    for (int mf = 0; mf < 4; mf++) {
        int r = m0 + wm + mf * 16 + grp;
#pragma unroll
        for (int nf = 0; nf < 8; nf++) {
            int c = n0 + wn + nf * 8 + tq * 2;
            float b0 = bias[c], b1 = bias[c + 1];
            float v0 = acc[mf][nf][0] + b0, v1 = acc[mf][nf][1] + b1;
            float v2 = acc[mf][nf][2] + b0, v3 = acc[mf][nf][3] + b1;
            if (outh) {
                *(__half2*)&outh[(size_t)r * Nc + c]       = __floats2half2_rn(v0, v1);
                *(__half2*)&outh[(size_t)(r + 8) * Nc + c] = __floats2half2_rn(v2, v3);
            } else {
                float2 r0 = __half22float2(*(const __half2*)&resid[(size_t)r * Nc + c]);
                float2 r1 = __half22float2(*(const __half2*)&resid[(size_t)(r + 8) * Nc + c]);
                v0 += r0.x; v1 += r0.y;
                v2 += r1.x; v3 += r1.y;
                *(float2*)&outf[(size_t)r * Nc + c]       = make_float2(v0, v1);
                *(float2*)&outf[(size_t)(r + 8) * Nc + c] = make_float2(v2, v3);
            }
        }
    }
}

// ---------------- fused attention (fp16): 128-query tile, register softmax ----------
// Warp owns 16 q-rows x 256 ctx. S in registers; exp via ex2.approx.f16x2 whose
// output IS the mma A-fragment; normalization deferred to the O epilogue.
extern __shared__ __half att_sm[];
__global__ __launch_bounds__(256, 1) void attn_kernel(
    const __half* __restrict__ Q, const __half* __restrict__ KV,
    __half* __restrict__ O)
{
    __half* Qs = att_sm;               // [128][72]
    __half* Ks = att_sm + 128 * 72;    // [256][72]
    __half* Vt = Ks + 256 * 72;        // [64][264]  (V transposed: [hd][ctx])

    int b = blockIdx.z, h = blockIdx.y, qt = blockIdx.x;
    int tid = threadIdx.x, w = tid >> 5, lane = tid & 31, grp = lane >> 2, tq = lane & 3;
    const int lr = lane & 7, sect = lane >> 3;
    const int sa_row = (sect & 1) * 8 + lr, sa_col = (sect >> 1) * 8;
    const int sb_row = (sect >> 1) * 8 + lr, sb_col = (sect & 1) * 8;
    size_t qbase  = ((size_t)(b * NB + qt * 128)) * DIM + h * HD;
    size_t kvbase = ((size_t)(b * MCTX)) * (2 * DIM) + h * HD;

    // Q, K via cp.async (8-half segments)
#pragma unroll
    for (int j = 0; j < 4; j++) {
        int lin = tid + j * 256;
        int m = lin >> 3, seg = lin & 7;
        cpa16(Qs + m * 72 + seg * 8, Q + qbase + (size_t)m * DIM + seg * 8);
    }
#pragma unroll
    for (int j = 0; j < 8; j++) {
        int lin = tid + j * 256;
        int m = lin >> 3, seg = lin & 7;
        cpa16(Ks + m * 72 + seg * 8, KV + kvbase + (size_t)m * (2 * DIM) + seg * 8);
    }
    cp_commit();
    // V transposed store (plain loads; V at +DIM in the KV row)
#pragma unroll
    for (int j = 0; j < 32; j++) {
        int idx = tid + j * 256;
        int m = idx & 255, cp = idx >> 8;
        __half2 hv = *(const __half2*)(KV + kvbase + DIM + (size_t)m * (2 * DIM) + cp * 2);
        Vt[(2 * cp) * 264 + m]     = __low2half(hv);
        Vt[(2 * cp + 1) * 264 + m] = __high2half(hv);
    }
    cp_wait<0>();
    __syncthreads();

    const int r0 = w * 16;

    float p[32][4];
#pragma unroll
    for (int f = 0; f < 32; f++)
#pragma unroll
        for (int r = 0; r < 4; r++) p[f][r] = 0.f;

#pragma unroll
    for (int ks = 0; ks < 4; ks++) {
        uint32_t a[4];
        ldsm4(a, Qs + (r0 + sa_row) * 72 + ks * 16 + sa_col);
#pragma unroll
        for (int fp = 0; fp < 16; fp++) {
            uint32_t t[4];
            ldsm4(t, Ks + (fp * 16 + sb_row) * 72 + ks * 16 + sb_col);
            mma16(p[2 * fp], a, t);
            mma16(p[2 * fp + 1], a, t + 2);
        }
    }

    // ---- softmax: fp32 max -> fp16x2 exp2 (unnormalized P = A-fragments)
    float mxA = -1e30f, mxB = -1e30f;
#pragma unroll
    for (int f = 0; f < 32; f++) {
        mxA = fmaxf(mxA, fmaxf(p[f][0], p[f][1]));
        mxB = fmaxf(mxB, fmaxf(p[f][2], p[f][3]));
    }
    mxA = fmaxf(mxA, __shfl_xor_sync(0xffffffffu, mxA, 1));
    mxA = fmaxf(mxA, __shfl_xor_sync(0xffffffffu, mxA, 2));
    mxB = fmaxf(mxB, __shfl_xor_sync(0xffffffffu, mxB, 1));
    mxB = fmaxf(mxB, __shfl_xor_sync(0xffffffffu, mxB, 2));
    const float mAc = mxA * ATT_C2, mBc = mxB * ATT_C2;

    uint32_t ph[32][2];
    float sA = 0.f, sB = 0.f;
#pragma unroll
    for (int f = 0; f < 32; f++) {
        ph[f][0] = ex2h2(packh2(fmaf(p[f][0], ATT_C2, -mAc), fmaf(p[f][1], ATT_C2, -mAc)));
        ph[f][1] = ex2h2(packh2(fmaf(p[f][2], ATT_C2, -mBc), fmaf(p[f][3], ATT_C2, -mBc)));
        float2 eA = __half22float2(*(__half2*)&ph[f][0]);
        float2 eB = __half22float2(*(__half2*)&ph[f][1]);
        sA += eA.x + eA.y;
        sB += eB.x + eB.y;
    }
    sA += __shfl_xor_sync(0xffffffffu, sA, 1);
    sA += __shfl_xor_sync(0xffffffffu, sA, 2);
    sB += __shfl_xor_sync(0xffffffffu, sB, 1);
    sB += __shfl_xor_sync(0xffffffffu, sB, 2);
    const float iA = 1.f / sA, iB = 1.f / sB;

    // ---- O = P_unnorm @ V
    float o[8][4];
#pragma unroll
    for (int f = 0; f < 8; f++)
#pragma unroll
        for (int r = 0; r < 4; r++) o[f][r] = 0.f;

#pragma unroll
    for (int kt = 0; kt < 16; kt++) {
        uint32_t a[4];
        a[0] = ph[2 * kt][0];
        a[1] = ph[2 * kt][1];
        a[2] = ph[2 * kt + 1][0];
        a[3] = ph[2 * kt + 1][1];
#pragma unroll
        for (int f2p = 0; f2p < 4; f2p++) {
            uint32_t t[4];
            ldsm4(t, Vt + (f2p * 16 + sb_row) * 264 + kt * 16 + sb_col);
            mma16(o[2 * f2p], a, t);
            mma16(o[2 * f2p + 1], a, t + 2);
        }
    }

    // epilogue: normalize rows here, write fp16
#pragma unroll
    for (int f2 = 0; f2 < 8; f2++) {
        int col = f2 * 8 + tq * 2;
        *(__half2*)&O[qbase + (size_t)(r0 + grp) * DIM + col] =
            __floats2half2_rn(o[f2][0] * iA, o[f2][1] * iA);
        *(__half2*)&O[qbase + (size_t)(r0 + grp + 8) * DIM + col] =
            __floats2half2_rn(o[f2][2] * iB, o[f2][3] * iB);
    }
}

// ---------------- launcher ----------------
extern "C" void kernel_launch(void* const* d_in, const int* in_sizes, int n_in,
                              void* d_out, int out_size)
{
    const float* features = (const float*)d_in[0];
    // d_in[1] = batch_indices: sorted, equal counts -> batch = row / NB (arithmetic)
    const float* context = (const float*)d_in[2];
    const float* Wq = (const float*)d_in[3];
    const float* bq = (const float*)d_in[4];
    const float* Wk = (const float*)d_in[5];
    const float* bk = (const float*)d_in[6];
    const float* Wv = (const float*)d_in[7];
    const float* bv = (const float*)d_in[8];
    const float* Wout = (const float*)d_in[9];
    const float* bout = (const float*)d_in[10];
    const float* ln_g = (const float*)d_in[11];
    const float* ln_b = (const float*)d_in[12];
    float* out = (float*)d_out;

    __half *fh_p, *q_p, *kv_p, *att_p, *ctx_p, *wt_p;
    float* bkv_p;
    cudaGetSymbolAddress((void**)&fh_p, g_fh);
    cudaGetSymbolAddress((void**)&q_p, g_q);
    cudaGetSymbolAddress((void**)&kv_p, g_kv);
    cudaGetSymbolAddress((void**)&att_p, g_att);
    cudaGetSymbolAddress((void**)&ctx_p, g_ctx);
    cudaGetSymbolAddress((void**)&wt_p, g_wt);
    cudaGetSymbolAddress((void**)&bkv_p, g_bkv);

    cudaFuncSetAttribute(attn_kernel, cudaFuncAttributeMaxDynamicSharedMemorySize, 89088);

    cvt_h_kernel<<<2048, 256>>>(context, ctx_p, BATCH * MCTX * CDIM);
    cvt_t4_kernel<<<dim3(CDIM / 32, DIM / 32, 4), 256>>>(Wk, Wv, Wq, Wout, wt_p);
    bias_cat_kernel<<<4, 256>>>(bk, bv, bkv_p);

    // 1. LayerNorm (fp16 output; also the residual source)
    ln_kernel<<<N_TOK / 8, 256>>>(features, ln_g, ln_b, fh_p);
    // 2. K+V projection in ONE gemm: (2048, 768) @ (768, 1024) -> g_kv
    gemm_h<<<dim3((2 * DIM) / 128, (BATCH * MCTX) / 128), 128>>>(
        ctx_p, wt_p + WT_WK, bkv_p, nullptr, kv_p, nullptr, CDIM, 2 * DIM);
    // 3. Q projection: (131072, 512) @ (512, 512)
    gemm_h<<<dim3(DIM / 128, N_TOK / 128), 128>>>(
        fh_p, wt_p + WT_WQ, bq, nullptr, q_p, nullptr, DIM, DIM);
    // 4. Attention
    attn_kernel<<<dim3(NB / 128, NH, BATCH), 256, 89088>>>(q_p, kv_p, att_p);
    // 5. Output projection + bias + residual (fp32 out, fp16 residual)
    gemm_h<<<dim3(DIM / 128, N_TOK / 128), 128>>>(
        att_p, wt_p + WT_WOUT, bout, fh_p, nullptr, out, DIM, DIM);
}

// round 14
// speedup vs baseline: 2.4426x; 1.0565x over previous
#include <cuda_runtime.h>
#include <cuda_fp16.h>
#include <cstdint>

#define N_TOK 131072
#define BATCH 8
#define MCTX 256
#define DIM 512
#define CDIM 768
#define NH 8
#define HD 64
#define NB (N_TOK / BATCH)
// ATT_SCALE * log2(e) = 0.125 * 1.4426950408889634
#define ATT_C2 0.18033688011112043f

// ---------------- scratch (device globals; no runtime allocation) ----------------
__device__ __half g_fh[(size_t)N_TOK * DIM];     // LayerNorm output fp16 (A for Qproj + residual)
__device__ __half g_q[(size_t)N_TOK * DIM];      // Q projection fp16
__device__ __half g_kv[BATCH * MCTX * 2 * DIM];  // K|V combined: row m, cols [0,512)=K, [512,1024)=V
__device__ __half g_att[(size_t)N_TOK * DIM];    // attention out fp16
__device__ __half g_ctx[BATCH * MCTX * CDIM];    // context fp16
__device__ __half g_wt[2 * CDIM * DIM + 2 * DIM * DIM]; // WkT,WvT,WqT,WoutT fp16, K-major [N][K]
__device__ float  g_bkv[2 * DIM];                // bk || bv

#define WT_WK 0
#define WT_WV (CDIM * DIM)
#define WT_WQ (2 * CDIM * DIM)
#define WT_WOUT (2 * CDIM * DIM + DIM * DIM)

// ---------------- helpers ----------------
__device__ __forceinline__ void mma16(float* c, const uint32_t* a, const uint32_t* b) {
    asm volatile(
        "mma.sync.aligned.m16n8k16.row.col.f32.f16.f16.f32 "
        "{%0,%1,%2,%3},{%4,%5,%6,%7},{%8,%9},{%0,%1,%2,%3};"
        : "+f"(c[0]), "+f"(c[1]), "+f"(c[2]), "+f"(c[3])
        : "r"(a[0]), "r"(a[1]), "r"(a[2]), "r"(a[3]), "r"(b[0]), "r"(b[1]));
}

__device__ __forceinline__ void ldsm4(uint32_t* r, const __half* p) {
    uint32_t a = (uint32_t)__cvta_generic_to_shared(p);
    asm volatile("ldmatrix.sync.aligned.m8n8.x4.shared.b16 {%0,%1,%2,%3}, [%4];"
        : "=r"(r[0]), "=r"(r[1]), "=r"(r[2]), "=r"(r[3]) : "r"(a));
}

__device__ __forceinline__ void cpa16(void* dst, const void* src) {
    uint32_t d = (uint32_t)__cvta_generic_to_shared(dst);
    asm volatile("cp.async.cg.shared.global [%0], [%1], 16;" :: "r"(d), "l"(src));
}
__device__ __forceinline__ void cp_commit() { asm volatile("cp.async.commit_group;"); }
template <int NN>
__device__ __forceinline__ void cp_wait() { asm volatile("cp.async.wait_group %0;" :: "n"(NN)); }

__device__ __forceinline__ uint32_t packh2(float lo, float hi) {
    __half2 h = __floats2half2_rn(lo, hi);
    return *(uint32_t*)&h;
}
__device__ __forceinline__ uint32_t ex2h2(uint32_t x) {
    uint32_t r;
    asm("ex2.approx.f16x2 %0, %1;" : "=r"(r) : "r"(x));
    return r;
}
__device__ __forceinline__ float ex2f(float x) {
    float r;
    asm("ex2.approx.f32 %0, %1;" : "=f"(r) : "f"(x));
    return r;
}

// ---------------- fp16 convert kernels ----------------
__global__ __launch_bounds__(256) void cvt_h_kernel(
    const float* __restrict__ src, __half* __restrict__ dst, int n)
{
    int i = blockIdx.x * blockDim.x + threadIdx.x;
    int stride = gridDim.x * blockDim.x;
    for (; i < n; i += stride) dst[i] = __float2half_rn(src[i]);
}

// merged transpose + fp16 for the 4 weights: dst[n][k] = h(src[k][n])
__global__ __launch_bounds__(256) void cvt_t4_kernel(
    const float* __restrict__ s0, const float* __restrict__ s1,
    const float* __restrict__ s2, const float* __restrict__ s3,
    __half* __restrict__ wt)
{
    __shared__ float t[32][33];
    int z = blockIdx.z;
    const float* src = (z == 0) ? s0 : (z == 1) ? s1 : (z == 2) ? s2 : s3;
    int Kd = (z < 2) ? CDIM : DIM;
    size_t doff = (z == 0) ? WT_WK : (z == 1) ? WT_WV : (z == 2) ? WT_WQ : (size_t)WT_WOUT;
    int k0 = blockIdx.x * 32, n0 = blockIdx.y * 32;
    if (k0 >= Kd) return;
    __half* dst = wt + doff;
    int tx = threadIdx.x & 31, ty = threadIdx.x >> 5;
#pragma unroll
    for (int i = ty; i < 32; i += 8)
        t[i][tx] = src[(size_t)(k0 + i) * DIM + n0 + tx];
    __syncthreads();
#pragma unroll
    for (int i = ty; i < 32; i += 8)
        dst[(size_t)(n0 + i) * Kd + k0 + tx] = __float2half_rn(t[tx][i]);
}

__global__ void bias_cat_kernel(const float* __restrict__ bk, const float* __restrict__ bv,
                                float* __restrict__ dst)
{
    int i = threadIdx.x + blockIdx.x * blockDim.x;
    if (i < DIM) dst[i] = bk[i];
    else if (i < 2 * DIM) dst[i] = bv[i - DIM];
}

// ---------------- LayerNorm: one warp per row; writes fp16 only ----------------
__global__ __launch_bounds__(256) void ln_kernel(
    const float* __restrict__ x, const float* __restrict__ g,
    const float* __restrict__ b, __half* __restrict__ out_h)
{
    int row = blockIdx.x * 8 + (threadIdx.x >> 5);
    int lane = threadIdx.x & 31;
    const float4* xp = (const float4*)(x + (size_t)row * DIM);
    float4 v[4];
    float s = 0.f;
#pragma unroll
    for (int j = 0; j < 4; j++) {
        v[j] = xp[lane + j * 32];
        s += v[j].x + v[j].y + v[j].z + v[j].w;
    }
#pragma unroll
    for (int o = 16; o; o >>= 1) s += __shfl_xor_sync(0xffffffffu, s, o);
    float mu = s * (1.f / DIM);
    float s2 = 0.f;
#pragma unroll
    for (int j = 0; j < 4; j++) {
        float dx;
        dx = v[j].x - mu; s2 += dx * dx;
        dx = v[j].y - mu; s2 += dx * dx;
        dx = v[j].z - mu; s2 += dx * dx;
        dx = v[j].w - mu; s2 += dx * dx;
    }
#pragma unroll
    for (int o = 16; o; o >>= 1) s2 += __shfl_xor_sync(0xffffffffu, s2, o);
    float rstd = rsqrtf(s2 * (1.f / DIM) + 1e-5f);
    const float4* gp = (const float4*)g;
    const float4* bp = (const float4*)b;
    __half2* ohp = (__half2*)(out_h + (size_t)row * DIM);
#pragma unroll
    for (int j = 0; j < 4; j++) {
        int idx = lane + j * 32;
        float4 gg = gp[idx], bb = bp[idx];
        float ox = (v[j].x - mu) * rstd * gg.x + bb.x;
        float oy = (v[j].y - mu) * rstd * gg.y + bb.y;
        float oz = (v[j].z - mu) * rstd * gg.z + bb.z;
        float ow = (v[j].w - mu) * rstd * gg.w + bb.w;
        ohp[idx * 2]     = __floats2half2_rn(ox, oy);
        ohp[idx * 2 + 1] = __floats2half2_rn(oz, ow);
    }
}

// ---------------- fp16 GEMM (cp.async double-buffered, ldmatrix, 64x64 warp tiles) --
// out = A[M,K] @ Bt[N,K]^T + bias (+fp16 resid). A, Bt fp16 K-major.
__global__ __launch_bounds__(128, 2) void gemm_h(
    const __half* __restrict__ A, const __half* __restrict__ Bt,
    const float* __restrict__ bias, const __half* __restrict__ resid,
    __half* __restrict__ outh, float* __restrict__ outf, int K, int Nc)
{
    __shared__ __half As[2][128][40];
    __shared__ __half Bs[2][128][40];
    const int tid = threadIdx.x;
    const int w = tid >> 5, lane = tid & 31, grp = lane >> 2, tq = lane & 3;
    const int wm = (w & 1) * 64, wn = (w >> 1) * 64;
    const int m0 = blockIdx.y * 128, n0 = blockIdx.x * 128;
    const int lr = lane & 7, sect = lane >> 3;   // ldmatrix addressing
    const int sa_row = (sect & 1) * 8 + lr, sa_col = (sect >> 1) * 8;
    const int sb_row = (sect >> 1) * 8 + lr, sb_col = (sect & 1) * 8;

    float acc[4][8][4];
#pragma unroll
    for (int i = 0; i < 4; i++)
#pragma unroll
        for (int j = 0; j < 8; j++)
#pragma unroll
            for (int r = 0; r < 4; r++) acc[i][j][r] = 0.f;

    auto load_tile = [&](int buf, int k0) {
#pragma unroll
        for (int j = 0; j < 4; j++) {
            int lin = tid + j * 128;
            int row = lin >> 2, seg = lin & 3;
            cpa16(&As[buf][row][seg * 8], A + (size_t)(m0 + row) * K + k0 + seg * 8);
        }
#pragma unroll
        for (int j = 0; j < 4; j++) {
            int lin = tid + j * 128;
            int row = lin >> 2, seg = lin & 3;
            cpa16(&Bs[buf][row][seg * 8], Bt + (size_t)(n0 + row) * K + k0 + seg * 8);
        }
    };

    load_tile(0, 0);
    cp_commit();
    load_tile(1, 32);
    cp_commit();

    const int KT = K / 32;
    for (int kt = 0; kt < KT; kt++) {
        cp_wait<1>();
        __syncthreads();
        const int buf = kt & 1;
#pragma unroll
        for (int ks = 0; ks < 2; ks++) {
            uint32_t a[4][4], b[8][2];
#pragma unroll
            for (int mf = 0; mf < 4; mf++)
                ldsm4(a[mf], &As[buf][wm + mf * 16 + sa_row][ks * 16 + sa_col]);
#pragma unroll
            for (int nf2 = 0; nf2 < 4; nf2++) {
                uint32_t t[4];
                ldsm4(t, &Bs[buf][wn + nf2 * 16 + sb_row][ks * 16 + sb_col]);
                b[2 * nf2][0] = t[0]; b[2 * nf2][1] = t[1];
                b[2 * nf2 + 1][0] = t[2]; b[2 * nf2 + 1][1] = t[3];
            }
#pragma unroll
            for (int mf = 0; mf < 4; mf++)
#pragma unroll
                for (int nf = 0; nf < 8; nf++)
                    mma16(acc[mf][nf], a[mf], b[nf]);
        }
        __syncthreads();
        if (kt + 2 < KT) load_tile(buf, (kt + 2) * 32);
        cp_commit();
    }

    // epilogue
#pragma unroll
    for (int mf = 0; mf < 4; mf++) {
        int r = m0 + wm + mf * 16 + grp;
#pragma unroll
        for (int nf = 0; nf < 8; nf++) {
            int c = n0 + wn + nf * 8 + tq * 2;
            float b0 = bias[c], b1 = bias[c + 1];
            float v0 = acc[mf][nf][0] + b0, v1 = acc[mf][nf][1] + b1;
            float v2 = acc[mf][nf][2] + b0, v3 = acc[mf][nf][3] + b1;
            if (outh) {
                *(__half2*)&outh[(size_t)r * Nc + c]       = __floats2half2_rn(v0, v1);
                *(__half2*)&outh[(size_t)(r + 8) * Nc + c] = __floats2half2_rn(v2, v3);
            } else {
                float2 r0 = __half22float2(*(const __half2*)&resid[(size_t)r * Nc + c]);
                float2 r1 = __half22float2(*(const __half2*)&resid[(size_t)(r + 8) * Nc + c]);
                v0 += r0.x; v1 += r0.y;
                v2 += r1.x; v3 += r1.y;
                *(float2*)&outf[(size_t)r * Nc + c]       = make_float2(v0, v1);
                *(float2*)&outf[(size_t)(r + 8) * Nc + c] = make_float2(v2, v3);
            }
        }
    }
}

// ---------------- fused attention (fp16): flash-style chunked online softmax --------
// Warp owns 16 q-rows x 256 ctx, processed in 4 chunks of 64 ctx columns.
// Per chunk: S mma (fp32) -> online max/rescale -> exp2 fp16 (A-frags) -> O mma.
// Registers stay ~120 -> 2 CTAs/SM.
extern __shared__ __half att_sm[];
__global__ __launch_bounds__(256, 2) void attn_kernel(
    const __half* __restrict__ Q, const __half* __restrict__ KV,
    __half* __restrict__ O)
{
    __half* Qs = att_sm;               // [128][72]
    __half* Ks = att_sm + 128 * 72;    // [256][72]
    __half* Vt = Ks + 256 * 72;        // [64][264]  (V transposed: [hd][ctx])

    int b = blockIdx.z, h = blockIdx.y, qt = blockIdx.x;
    int tid = threadIdx.x, w = tid >> 5, lane = tid & 31, grp = lane >> 2, tq = lane & 3;
    const int lr = lane & 7, sect = lane >> 3;
    const int sa_row = (sect & 1) * 8 + lr, sa_col = (sect >> 1) * 8;
    const int sb_row = (sect >> 1) * 8 + lr, sb_col = (sect & 1) * 8;
    size_t qbase  = ((size_t)(b * NB + qt * 128)) * DIM + h * HD;
    size_t kvbase = ((size_t)(b * MCTX)) * (2 * DIM) + h * HD;

    // Q, K via cp.async (8-half segments)
#pragma unroll
    for (int j = 0; j < 4; j++) {
        int lin = tid + j * 256;
        int m = lin >> 3, seg = lin & 7;
        cpa16(Qs + m * 72 + seg * 8, Q + qbase + (size_t)m * DIM + seg * 8);
    }
#pragma unroll
    for (int j = 0; j < 8; j++) {
        int lin = tid + j * 256;
        int m = lin >> 3, seg = lin & 7;
        cpa16(Ks + m * 72 + seg * 8, KV + kvbase + (size_t)m * (2 * DIM) + seg * 8);
    }
    cp_commit();
    // V transposed store (plain loads; V at +DIM in the KV row)
#pragma unroll
    for (int j = 0; j < 32; j++) {
        int idx = tid + j * 256;
        int m = idx & 255, cp = idx >> 8;
        __half2 hv = *(const __half2*)(KV + kvbase + DIM + (size_t)m * (2 * DIM) + cp * 2);
        Vt[(2 * cp) * 264 + m]     = __low2half(hv);
        Vt[(2 * cp + 1) * 264 + m] = __high2half(hv);
    }
    cp_wait<0>();
    __syncthreads();

    const int r0 = w * 16;

    float o[8][4];
#pragma unroll
    for (int f = 0; f < 8; f++)
#pragma unroll
        for (int r = 0; r < 4; r++) o[f][r] = 0.f;
    float mA = -1e30f, mB = -1e30f, sA = 0.f, sB = 0.f;

#pragma unroll 1
    for (int c = 0; c < 4; c++) {
        // ---- S chunk = Q @ K[c*64 : c*64+64]^T
        float s[8][4];
#pragma unroll
        for (int f = 0; f < 8; f++)
#pragma unroll
            for (int r = 0; r < 4; r++) s[f][r] = 0.f;

#pragma unroll
        for (int ks = 0; ks < 4; ks++) {
            uint32_t a[4];
            ldsm4(a, Qs + (r0 + sa_row) * 72 + ks * 16 + sa_col);
#pragma unroll
            for (int fp = 0; fp < 4; fp++) {
                uint32_t t[4];
                ldsm4(t, Ks + (c * 64 + fp * 16 + sb_row) * 72 + ks * 16 + sb_col);
                mma16(s[2 * fp], a, t);
                mma16(s[2 * fp + 1], a, t + 2);
            }
        }

        // ---- online max + rescale
        float cA = -1e30f, cB = -1e30f;
#pragma unroll
        for (int f = 0; f < 8; f++) {
            cA = fmaxf(cA, fmaxf(s[f][0], s[f][1]));
            cB = fmaxf(cB, fmaxf(s[f][2], s[f][3]));
        }
        cA = fmaxf(cA, __shfl_xor_sync(0xffffffffu, cA, 1));
        cA = fmaxf(cA, __shfl_xor_sync(0xffffffffu, cA, 2));
        cB = fmaxf(cB, __shfl_xor_sync(0xffffffffu, cB, 1));
        cB = fmaxf(cB, __shfl_xor_sync(0xffffffffu, cB, 2));
        float nA = fmaxf(mA, cA * ATT_C2);
        float nB = fmaxf(mB, cB * ATT_C2);
        float fA = ex2f(mA - nA);
        float fB = ex2f(mB - nB);
        mA = nA; mB = nB;
        sA *= fA; sB *= fB;
#pragma unroll
        for (int f = 0; f < 8; f++) {
            o[f][0] *= fA; o[f][1] *= fA;
            o[f][2] *= fB; o[f][3] *= fB;
        }

        // ---- exp2 to fp16 (unnormalized P = A-fragments) + partial sums
        uint32_t ph[8][2];
#pragma unroll
        for (int f = 0; f < 8; f++) {
            ph[f][0] = ex2h2(packh2(fmaf(s[f][0], ATT_C2, -nA), fmaf(s[f][1], ATT_C2, -nA)));
            ph[f][1] = ex2h2(packh2(fmaf(s[f][2], ATT_C2, -nB), fmaf(s[f][3], ATT_C2, -nB)));
            float2 eA = __half22float2(*(__half2*)&ph[f][0]);
            float2 eB = __half22float2(*(__half2*)&ph[f][1]);
            sA += eA.x + eA.y;
            sB += eB.x + eB.y;
        }

        // ---- O += P_chunk @ V_chunk
#pragma unroll
        for (int kt = 0; kt < 4; kt++) {
            uint32_t a[4];
            a[0] = ph[2 * kt][0];
            a[1] = ph[2 * kt][1];
            a[2] = ph[2 * kt + 1][0];
            a[3] = ph[2 * kt + 1][1];
#pragma unroll
            for (int f2p = 0; f2p < 4; f2p++) {
                uint32_t t[4];
                ldsm4(t, Vt + (f2p * 16 + sb_row) * 264 + c * 64 + kt * 16 + sb_col);
                mma16(o[2 * f2p], a, t);
                mma16(o[2 * f2p + 1], a, t + 2);
            }
        }
    }

    // ---- final row sums (quad reduce) + normalize + store
    sA += __shfl_xor_sync(0xffffffffu, sA, 1);
    sA += __shfl_xor_sync(0xffffffffu, sA, 2);
    sB += __shfl_xor_sync(0xffffffffu, sB, 1);
    sB += __shfl_xor_sync(0xffffffffu, sB, 2);
    const float iA = 1.f / sA, iB = 1.f / sB;

#pragma unroll
    for (int f2 = 0; f2 < 8; f2++) {
        int col = f2 * 8 + tq * 2;
        *(__half2*)&O[qbase + (size_t)(r0 + grp) * DIM + col] =
            __floats2half2_rn(o[f2][0] * iA, o[f2][1] * iA);
        *(__half2*)&O[qbase + (size_t)(r0 + grp + 8) * DIM + col] =
            __floats2half2_rn(o[f2][2] * iB, o[f2][3] * iB);
    }
}

// ---------------- launcher ----------------
extern "C" void kernel_launch(void* const* d_in, const int* in_sizes, int n_in,
                              void* d_out, int out_size)
{
    const float* features = (const float*)d_in[0];
    // d_in[1] = batch_indices: sorted, equal counts -> batch = row / NB (arithmetic)
    const float* context = (const float*)d_in[2];
    const float* Wq = (const float*)d_in[3];
    const float* bq = (const float*)d_in[4];
    const float* Wk = (const float*)d_in[5];
    const float* bk = (const float*)d_in[6];
    const float* Wv = (const float*)d_in[7];
    const float* bv = (const float*)d_in[8];
    const float* Wout = (const float*)d_in[9];
    const float* bout = (const float*)d_in[10];
    const float* ln_g = (const float*)d_in[11];
    const float* ln_b = (const float*)d_in[12];
    float* out = (float*)d_out;

    __half *fh_p, *q_p, *kv_p, *att_p, *ctx_p, *wt_p;
    float* bkv_p;
    cudaGetSymbolAddress((void**)&fh_p, g_fh);
    cudaGetSymbolAddress((void**)&q_p, g_q);
    cudaGetSymbolAddress((void**)&kv_p, g_kv);
    cudaGetSymbolAddress((void**)&att_p, g_att);
    cudaGetSymbolAddress((void**)&ctx_p, g_ctx);
    cudaGetSymbolAddress((void**)&wt_p, g_wt);
    cudaGetSymbolAddress((void**)&bkv_p, g_bkv);

    cudaFuncSetAttribute(attn_kernel, cudaFuncAttributeMaxDynamicSharedMemorySize, 89088);

    cvt_h_kernel<<<2048, 256>>>(context, ctx_p, BATCH * MCTX * CDIM);
    cvt_t4_kernel<<<dim3(CDIM / 32, DIM / 32, 4), 256>>>(Wk, Wv, Wq, Wout, wt_p);
    bias_cat_kernel<<<4, 256>>>(bk, bv, bkv_p);

    // 1. LayerNorm (fp16 output; also the residual source)
    ln_kernel<<<N_TOK / 8, 256>>>(features, ln_g, ln_b, fh_p);
    // 2. K+V projection in ONE gemm: (2048, 768) @ (768, 1024) -> g_kv
    gemm_h<<<dim3((2 * DIM) / 128, (BATCH * MCTX) / 128), 128>>>(
        ctx_p, wt_p + WT_WK, bkv_p, nullptr, kv_p, nullptr, CDIM, 2 * DIM);
    // 3. Q projection: (131072, 512) @ (512, 512)
    gemm_h<<<dim3(DIM / 128, N_TOK / 128), 128>>>(
        fh_p, wt_p + WT_WQ, bq, nullptr, q_p, nullptr, DIM, DIM);
    // 4. Attention (flash-style online softmax, 2 CTAs/SM)
    attn_kernel<<<dim3(NB / 128, NH, BATCH), 256, 89088>>>(q_p, kv_p, att_p);
    // 5. Output projection + bias + residual (fp32 out, fp16 residual)
    gemm_h<<<dim3(DIM / 128, N_TOK / 128), 128>>>(
        att_p, wt_p + WT_WOUT, bout, fh_p, nullptr, out, DIM, DIM);
}

// round 16
// speedup vs baseline: 2.5884x; 1.0597x over previous
#include <cuda_runtime.h>
#include <cuda_fp16.h>
#include <cstdint>

#define N_TOK 131072
#define BATCH 8
#define MCTX 256
#define DIM 512
#define CDIM 768
#define NH 8
#define HD 64
#define NB (N_TOK / BATCH)
// ATT_SCALE * log2(e) = 0.125 * 1.4426950408889634
#define ATT_C2 0.18033688011112043f

// ---------------- scratch (device globals; no runtime allocation) ----------------
__device__ __half g_fh[(size_t)N_TOK * DIM];     // LayerNorm output fp16 (A for Qproj + residual)
__device__ __half g_q[(size_t)N_TOK * DIM];      // Q projection fp16
__device__ __half g_kv[BATCH * MCTX * 2 * DIM];  // K|V combined: row m, cols [0,512)=K, [512,1024)=V
__device__ __half g_att[(size_t)N_TOK * DIM];    // attention out fp16
__device__ __half g_ctx[BATCH * MCTX * CDIM];    // context fp16
__device__ __half g_wt[2 * CDIM * DIM + 2 * DIM * DIM]; // WkT,WvT,WqT,WoutT fp16, K-major [N][K]
__device__ float  g_bkv[2 * DIM];                // bk || bv

#define WT_WK 0
#define WT_WV (CDIM * DIM)
#define WT_WQ (2 * CDIM * DIM)
#define WT_WOUT (2 * CDIM * DIM + DIM * DIM)

// ---------------- helpers ----------------
__device__ __forceinline__ void mma16(float* c, const uint32_t* a, const uint32_t* b) {
    asm volatile(
        "mma.sync.aligned.m16n8k16.row.col.f32.f16.f16.f32 "
        "{%0,%1,%2,%3},{%4,%5,%6,%7},{%8,%9},{%0,%1,%2,%3};"
        : "+f"(c[0]), "+f"(c[1]), "+f"(c[2]), "+f"(c[3])
        : "r"(a[0]), "r"(a[1]), "r"(a[2]), "r"(a[3]), "r"(b[0]), "r"(b[1]));
}

__device__ __forceinline__ void ldsm4(uint32_t* r, const __half* p) {
    uint32_t a = (uint32_t)__cvta_generic_to_shared(p);
    asm volatile("ldmatrix.sync.aligned.m8n8.x4.shared.b16 {%0,%1,%2,%3}, [%4];"
        : "=r"(r[0]), "=r"(r[1]), "=r"(r[2]), "=r"(r[3]) : "r"(a));
}

__device__ __forceinline__ void cpa16(void* dst, const void* src) {
    uint32_t d = (uint32_t)__cvta_generic_to_shared(dst);
    asm volatile("cp.async.cg.shared.global [%0], [%1], 16;" :: "r"(d), "l"(src));
}
__device__ __forceinline__ void cp_commit() { asm volatile("cp.async.commit_group;"); }
template <int NN>
__device__ __forceinline__ void cp_wait() { asm volatile("cp.async.wait_group %0;" :: "n"(NN)); }

__device__ __forceinline__ uint32_t packh2(float lo, float hi) {
    __half2 h = __floats2half2_rn(lo, hi);
    return *(uint32_t*)&h;
}
__device__ __forceinline__ uint32_t ex2h2(uint32_t x) {
    uint32_t r;
    asm("ex2.approx.f16x2 %0, %1;" : "=r"(r) : "r"(x));
    return r;
}
__device__ __forceinline__ float ex2f(float x) {
    float r;
    asm("ex2.approx.f32 %0, %1;" : "=f"(r) : "f"(x));
    return r;
}

// ---------------- fp16 convert kernels ----------------
__global__ __launch_bounds__(256) void cvt_h_kernel(
    const float* __restrict__ src, __half* __restrict__ dst, int n)
{
    int i = blockIdx.x * blockDim.x + threadIdx.x;
    int stride = gridDim.x * blockDim.x;
    for (; i < n; i += stride) dst[i] = __float2half_rn(src[i]);
}

// merged transpose + fp16 for the 4 weights: dst[n][k] = h(src[k][n])
__global__ __launch_bounds__(256) void cvt_t4_kernel(
    const float* __restrict__ s0, const float* __restrict__ s1,
    const float* __restrict__ s2, const float* __restrict__ s3,
    __half* __restrict__ wt)
{
    __shared__ float t[32][33];
    int z = blockIdx.z;
    const float* src = (z == 0) ? s0 : (z == 1) ? s1 : (z == 2) ? s2 : s3;
    int Kd = (z < 2) ? CDIM : DIM;
    size_t doff = (z == 0) ? WT_WK : (z == 1) ? WT_WV : (z == 2) ? WT_WQ : (size_t)WT_WOUT;
    int k0 = blockIdx.x * 32, n0 = blockIdx.y * 32;
    if (k0 >= Kd) return;
    __half* dst = wt + doff;
    int tx = threadIdx.x & 31, ty = threadIdx.x >> 5;
#pragma unroll
    for (int i = ty; i < 32; i += 8)
        t[i][tx] = src[(size_t)(k0 + i) * DIM + n0 + tx];
    __syncthreads();
#pragma unroll
    for (int i = ty; i < 32; i += 8)
        dst[(size_t)(n0 + i) * Kd + k0 + tx] = __float2half_rn(t[tx][i]);
}

__global__ void bias_cat_kernel(const float* __restrict__ bk, const float* __restrict__ bv,
                                float* __restrict__ dst)
{
    int i = threadIdx.x + blockIdx.x * blockDim.x;
    if (i < DIM) dst[i] = bk[i];
    else if (i < 2 * DIM) dst[i] = bv[i - DIM];
}

// ---------------- LayerNorm: one warp per row; writes fp16 only ----------------
__global__ __launch_bounds__(256) void ln_kernel(
    const float* __restrict__ x, const float* __restrict__ g,
    const float* __restrict__ b, __half* __restrict__ out_h)
{
    int row = blockIdx.x * 8 + (threadIdx.x >> 5);
    int lane = threadIdx.x & 31;
    const float4* xp = (const float4*)(x + (size_t)row * DIM);
    float4 v[4];
    float s = 0.f;
#pragma unroll
    for (int j = 0; j < 4; j++) {
        v[j] = xp[lane + j * 32];
        s += v[j].x + v[j].y + v[j].z + v[j].w;
    }
#pragma unroll
    for (int o = 16; o; o >>= 1) s += __shfl_xor_sync(0xffffffffu, s, o);
    float mu = s * (1.f / DIM);
    float s2 = 0.f;
#pragma unroll
    for (int j = 0; j < 4; j++) {
        float dx;
        dx = v[j].x - mu; s2 += dx * dx;
        dx = v[j].y - mu; s2 += dx * dx;
        dx = v[j].z - mu; s2 += dx * dx;
        dx = v[j].w - mu; s2 += dx * dx;
    }
#pragma unroll
    for (int o = 16; o; o >>= 1) s2 += __shfl_xor_sync(0xffffffffu, s2, o);
    float rstd = rsqrtf(s2 * (1.f / DIM) + 1e-5f);
    const float4* gp = (const float4*)g;
    const float4* bp = (const float4*)b;
    __half2* ohp = (__half2*)(out_h + (size_t)row * DIM);
#pragma unroll
    for (int j = 0; j < 4; j++) {
        int idx = lane + j * 32;
        float4 gg = gp[idx], bb = bp[idx];
        float ox = (v[j].x - mu) * rstd * gg.x + bb.x;
        float oy = (v[j].y - mu) * rstd * gg.y + bb.y;
        float oz = (v[j].z - mu) * rstd * gg.z + bb.z;
        float ow = (v[j].w - mu) * rstd * gg.w + bb.w;
        ohp[idx * 2]     = __floats2half2_rn(ox, oy);
        ohp[idx * 2 + 1] = __floats2half2_rn(oz, ow);
    }
}

// ---------------- fp16 GEMM: 3-stage cp.async ring, ldmatrix, 64x64 warp tiles -----
// out = A[M,K] @ Bt[N,K]^T + bias (+fp16 resid). A, Bt fp16 K-major.
// Block 128x128, 128 threads, 4 warps (2m x 2n). One __syncthreads per ktile.
// 3 CTAs/SM (60KB dynamic smem each).
#define GH_OP 5120                 // halves per operand per stage (128 rows x 40)
#define GH_STAGE (2 * GH_OP)       // halves per stage (A + B)
#define GH_SMEM (3 * GH_STAGE * 2) // bytes: 61440

extern __shared__ __half gh_sm[];
__global__ __launch_bounds__(128, 3) void gemm_h(
    const __half* __restrict__ A, const __half* __restrict__ Bt,
    const float* __restrict__ bias, const __half* __restrict__ resid,
    __half* __restrict__ outh, float* __restrict__ outf, int K, int Nc)
{
    const int tid = threadIdx.x;
    const int w = tid >> 5, lane = tid & 31, grp = lane >> 2, tq = lane & 3;
    const int wm = (w & 1) * 64, wn = (w >> 1) * 64;
    const int m0 = blockIdx.y * 128, n0 = blockIdx.x * 128;
    const int lr = lane & 7, sect = lane >> 3;   // ldmatrix addressing
    const int sa_row = (sect & 1) * 8 + lr, sa_col = (sect >> 1) * 8;
    const int sb_row = (sect >> 1) * 8 + lr, sb_col = (sect & 1) * 8;

    float acc[4][8][4];
#pragma unroll
    for (int i = 0; i < 4; i++)
#pragma unroll
        for (int j = 0; j < 8; j++)
#pragma unroll
            for (int r = 0; r < 4; r++) acc[i][j][r] = 0.f;

    auto load_tile = [&](int st, int k0) {
        __half* Ab = gh_sm + st * GH_STAGE;
        __half* Bb = Ab + GH_OP;
#pragma unroll
        for (int j = 0; j < 4; j++) {
            int lin = tid + j * 128;
            int row = lin >> 2, seg = lin & 3;
            cpa16(Ab + row * 40 + seg * 8, A + (size_t)(m0 + row) * K + k0 + seg * 8);
        }
#pragma unroll
        for (int j = 0; j < 4; j++) {
            int lin = tid + j * 128;
            int row = lin >> 2, seg = lin & 3;
            cpa16(Bb + row * 40 + seg * 8, Bt + (size_t)(n0 + row) * K + k0 + seg * 8);
        }
        cp_commit();
    };

    load_tile(0, 0);
    load_tile(1, 32);

    const int KT = K / 32;
#pragma unroll 1
    for (int kt = 0; kt < KT; kt++) {
        if (kt == KT - 1) cp_wait<0>(); else cp_wait<1>();
        __syncthreads();
        const __half* Ab = gh_sm + (kt % 3) * GH_STAGE;
        const __half* Bb = Ab + GH_OP;
#pragma unroll
        for (int ks = 0; ks < 2; ks++) {
            uint32_t a[4][4], b[8][2];
#pragma unroll
            for (int mf = 0; mf < 4; mf++)
                ldsm4(a[mf], Ab + (wm + mf * 16 + sa_row) * 40 + ks * 16 + sa_col);
#pragma unroll
            for (int nf2 = 0; nf2 < 4; nf2++) {
                uint32_t t[4];
                ldsm4(t, Bb + (wn + nf2 * 16 + sb_row) * 40 + ks * 16 + sb_col);
                b[2 * nf2][0] = t[0]; b[2 * nf2][1] = t[1];
                b[2 * nf2 + 1][0] = t[2]; b[2 * nf2 + 1][1] = t[3];
            }
#pragma unroll
            for (int mf = 0; mf < 4; mf++)
#pragma unroll
                for (int nf = 0; nf < 8; nf++)
                    mma16(acc[mf][nf], a[mf], b[nf]);
        }
        // loads for kt+2 go into stage (kt+2)%3, last read at iter kt-1 (pre-barrier)
        if (kt + 2 < KT) load_tile((kt + 2) % 3, (kt + 2) * 32);
    }

    // epilogue
#pragma unroll
    for (int mf = 0; mf < 4; mf++) {
        int r = m0 + wm + mf * 16 + grp;
#pragma unroll
        for (int nf = 0; nf < 8; nf++) {
            int c = n0 + wn + nf * 8 + tq * 2;
            float b0 = bias[c], b1 = bias[c + 1];
            float v0 = acc[mf][nf][0] + b0, v1 = acc[mf][nf][1] + b1;
            float v2 = acc[mf][nf][2] + b0, v3 = acc[mf][nf][3] + b1;
            if (outh) {
                *(__half2*)&outh[(size_t)r * Nc + c]       = __floats2half2_rn(v0, v1);
                *(__half2*)&outh[(size_t)(r + 8) * Nc + c] = __floats2half2_rn(v2, v3);
            } else {
                float2 r0 = __half22float2(*(const __half2*)&resid[(size_t)r * Nc + c]);
                float2 r1 = __half22float2(*(const __half2*)&resid[(size_t)(r + 8) * Nc + c]);
                v0 += r0.x; v1 += r0.y;
                v2 += r1.x; v3 += r1.y;
                *(float2*)&outf[(size_t)r * Nc + c]       = make_float2(v0, v1);
                *(float2*)&outf[(size_t)(r + 8) * Nc + c] = make_float2(v2, v3);
            }
        }
    }
}

// ---------------- fused attention (fp16): flash-style chunked online softmax --------
// Warp owns 16 q-rows x 256 ctx, processed in 4 chunks of 64 ctx columns.
extern __shared__ __half att_sm[];
__global__ __launch_bounds__(256, 2) void attn_kernel(
    const __half* __restrict__ Q, const __half* __restrict__ KV,
    __half* __restrict__ O)
{
    __half* Qs = att_sm;               // [128][72]
    __half* Ks = att_sm + 128 * 72;    // [256][72]
    __half* Vt = Ks + 256 * 72;        // [64][264]  (V transposed: [hd][ctx])

    int b = blockIdx.z, h = blockIdx.y, qt = blockIdx.x;
    int tid = threadIdx.x, w = tid >> 5, lane = tid & 31, grp = lane >> 2, tq = lane & 3;
    const int lr = lane & 7, sect = lane >> 3;
    const int sa_row = (sect & 1) * 8 + lr, sa_col = (sect >> 1) * 8;
    const int sb_row = (sect >> 1) * 8 + lr, sb_col = (sect & 1) * 8;
    size_t qbase  = ((size_t)(b * NB + qt * 128)) * DIM + h * HD;
    size_t kvbase = ((size_t)(b * MCTX)) * (2 * DIM) + h * HD;

    // Q, K via cp.async (8-half segments)
#pragma unroll
    for (int j = 0; j < 4; j++) {
        int lin = tid + j * 256;
        int m = lin >> 3, seg = lin & 7;
        cpa16(Qs + m * 72 + seg * 8, Q + qbase + (size_t)m * DIM + seg * 8);
    }
#pragma unroll
    for (int j = 0; j < 8; j++) {
        int lin = tid + j * 256;
        int m = lin >> 3, seg = lin & 7;
        cpa16(Ks + m * 72 + seg * 8, KV + kvbase + (size_t)m * (2 * DIM) + seg * 8);
    }
    cp_commit();
    // V transposed store (plain loads; V at +DIM in the KV row)
#pragma unroll
    for (int j = 0; j < 32; j++) {
        int idx = tid + j * 256;
        int m = idx & 255, cp = idx >> 8;
        __half2 hv = *(const __half2*)(KV + kvbase + DIM + (size_t)m * (2 * DIM) + cp * 2);
        Vt[(2 * cp) * 264 + m]     = __low2half(hv);
        Vt[(2 * cp + 1) * 264 + m] = __high2half(hv);
    }
    cp_wait<0>();
    __syncthreads();

    const int r0 = w * 16;

    float o[8][4];
#pragma unroll
    for (int f = 0; f < 8; f++)
#pragma unroll
        for (int r = 0; r < 4; r++) o[f][r] = 0.f;
    float mA = -1e30f, mB = -1e30f, sA = 0.f, sB = 0.f;

#pragma unroll 1
    for (int c = 0; c < 4; c++) {
        // ---- S chunk = Q @ K[c*64 : c*64+64]^T
        float s[8][4];
#pragma unroll
        for (int f = 0; f < 8; f++)
#pragma unroll
            for (int r = 0; r < 4; r++) s[f][r] = 0.f;

#pragma unroll
        for (int ks = 0; ks < 4; ks++) {
            uint32_t a[4];
            ldsm4(a, Qs + (r0 + sa_row) * 72 + ks * 16 + sa_col);
#pragma unroll
            for (int fp = 0; fp < 4; fp++) {
                uint32_t t[4];
                ldsm4(t, Ks + (c * 64 + fp * 16 + sb_row) * 72 + ks * 16 + sb_col);
                mma16(s[2 * fp], a, t);
                mma16(s[2 * fp + 1], a, t + 2);
            }
        }

        // ---- online max + rescale
        float cA = -1e30f, cB = -1e30f;
#pragma unroll
        for (int f = 0; f < 8; f++) {
            cA = fmaxf(cA, fmaxf(s[f][0], s[f][1]));
            cB = fmaxf(cB, fmaxf(s[f][2], s[f][3]));
        }
        cA = fmaxf(cA, __shfl_xor_sync(0xffffffffu, cA, 1));
        cA = fmaxf(cA, __shfl_xor_sync(0xffffffffu, cA, 2));
        cB = fmaxf(cB, __shfl_xor_sync(0xffffffffu, cB, 1));
        cB = fmaxf(cB, __shfl_xor_sync(0xffffffffu, cB, 2));
        float nA = fmaxf(mA, cA * ATT_C2);
        float nB = fmaxf(mB, cB * ATT_C2);
        float fA = ex2f(mA - nA);
        float fB = ex2f(mB - nB);
        mA = nA; mB = nB;
        sA *= fA; sB *= fB;
#pragma unroll
        for (int f = 0; f < 8; f++) {
            o[f][0] *= fA; o[f][1] *= fA;
            o[f][2] *= fB; o[f][3] *= fB;
        }

        // ---- exp2 to fp16 (unnormalized P = A-fragments) + partial sums
        uint32_t ph[8][2];
#pragma unroll
        for (int f = 0; f < 8; f++) {
            ph[f][0] = ex2h2(packh2(fmaf(s[f][0], ATT_C2, -nA), fmaf(s[f][1], ATT_C2, -nA)));
            ph[f][1] = ex2h2(packh2(fmaf(s[f][2], ATT_C2, -nB), fmaf(s[f][3], ATT_C2, -nB)));
            float2 eA = __half22float2(*(__half2*)&ph[f][0]);
            float2 eB = __half22float2(*(__half2*)&ph[f][1]);
            sA += eA.x + eA.y;
            sB += eB.x + eB.y;
        }

        // ---- O += P_chunk @ V_chunk
#pragma unroll
        for (int kt = 0; kt < 4; kt++) {
            uint32_t a[4];
            a[0] = ph[2 * kt][0];
            a[1] = ph[2 * kt][1];
            a[2] = ph[2 * kt + 1][0];
            a[3] = ph[2 * kt + 1][1];
#pragma unroll
            for (int f2p = 0; f2p < 4; f2p++) {
                uint32_t t[4];
                ldsm4(t, Vt + (f2p * 16 + sb_row) * 264 + c * 64 + kt * 16 + sb_col);
                mma16(o[2 * f2p], a, t);
                mma16(o[2 * f2p + 1], a, t + 2);
            }
        }
    }

    // ---- final row sums (quad reduce) + normalize + store
    sA += __shfl_xor_sync(0xffffffffu, sA, 1);
    sA += __shfl_xor_sync(0xffffffffu, sA, 2);
    sB += __shfl_xor_sync(0xffffffffu, sB, 1);
    sB += __shfl_xor_sync(0xffffffffu, sB, 2);
    const float iA = 1.f / sA, iB = 1.f / sB;

#pragma unroll
    for (int f2 = 0; f2 < 8; f2++) {
        int col = f2 * 8 + tq * 2;
        *(__half2*)&O[qbase + (size_t)(r0 + grp) * DIM + col] =
            __floats2half2_rn(o[f2][0] * iA, o[f2][1] * iA);
        *(__half2*)&O[qbase + (size_t)(r0 + grp + 8) * DIM + col] =
            __floats2half2_rn(o[f2][2] * iB, o[f2][3] * iB);
    }
}

// ---------------- launcher ----------------
extern "C" void kernel_launch(void* const* d_in, const int* in_sizes, int n_in,
                              void* d_out, int out_size)
{
    const float* features = (const float*)d_in[0];
    // d_in[1] = batch_indices: sorted, equal counts -> batch = row / NB (arithmetic)
    const float* context = (const float*)d_in[2];
    const float* Wq = (const float*)d_in[3];
    const float* bq = (const float*)d_in[4];
    const float* Wk = (const float*)d_in[5];
    const float* bk = (const float*)d_in[6];
    const float* Wv = (const float*)d_in[7];
    const float* bv = (const float*)d_in[8];
    const float* Wout = (const float*)d_in[9];
    const float* bout = (const float*)d_in[10];
    const float* ln_g = (const float*)d_in[11];
    const float* ln_b = (const float*)d_in[12];
    float* out = (float*)d_out;

    __half *fh_p, *q_p, *kv_p, *att_p, *ctx_p, *wt_p;
    float* bkv_p;
    cudaGetSymbolAddress((void**)&fh_p, g_fh);
    cudaGetSymbolAddress((void**)&q_p, g_q);
    cudaGetSymbolAddress((void**)&kv_p, g_kv);
    cudaGetSymbolAddress((void**)&att_p, g_att);
    cudaGetSymbolAddress((void**)&ctx_p, g_ctx);
    cudaGetSymbolAddress((void**)&wt_p, g_wt);
    cudaGetSymbolAddress((void**)&bkv_p, g_bkv);

    cudaFuncSetAttribute(gemm_h, cudaFuncAttributeMaxDynamicSharedMemorySize, GH_SMEM);
    cudaFuncSetAttribute(attn_kernel, cudaFuncAttributeMaxDynamicSharedMemorySize, 89088);

    cvt_h_kernel<<<2048, 256>>>(context, ctx_p, BATCH * MCTX * CDIM);
    cvt_t4_kernel<<<dim3(CDIM / 32, DIM / 32, 4), 256>>>(Wk, Wv, Wq, Wout, wt_p);
    bias_cat_kernel<<<4, 256>>>(bk, bv, bkv_p);

    // 1. LayerNorm (fp16 output; also the residual source)
    ln_kernel<<<N_TOK / 8, 256>>>(features, ln_g, ln_b, fh_p);
    // 2. K+V projection in ONE gemm: (2048, 768) @ (768, 1024) -> g_kv
    gemm_h<<<dim3((2 * DIM) / 128, (BATCH * MCTX) / 128), 128, GH_SMEM>>>(
        ctx_p, wt_p + WT_WK, bkv_p, nullptr, kv_p, nullptr, CDIM, 2 * DIM);
    // 3. Q projection: (131072, 512) @ (512, 512)
    gemm_h<<<dim3(DIM / 128, N_TOK / 128), 128, GH_SMEM>>>(
        fh_p, wt_p + WT_WQ, bq, nullptr, q_p, nullptr, DIM, DIM);
    // 4. Attention (flash-style online softmax, 2 CTAs/SM)
    attn_kernel<<<dim3(NB / 128, NH, BATCH), 256, 89088>>>(q_p, kv_p, att_p);
    // 5. Output projection + bias + residual (fp32 out, fp16 residual)
    gemm_h<<<dim3(DIM / 128, N_TOK / 128), 128, GH_SMEM>>>(
        att_p, wt_p + WT_WOUT, bout, fh_p, nullptr, out, DIM, DIM);
}

// round 17
// speedup vs baseline: 3.1518x; 1.2176x over previous
#include <cuda_runtime.h>
#include <cuda_fp16.h>
#include <cstdint>

#define N_TOK 131072
#define BATCH 8
#define MCTX 256
#define DIM 512
#define CDIM 768
#define NH 8
#define HD 64
#define NB (N_TOK / BATCH)
// ATT_SCALE * log2(e) = 0.125 * 1.4426950408889634
#define ATT_C2 0.18033688011112043f

// ---------------- scratch (device globals; no runtime allocation) ----------------
__device__ __half g_fh[(size_t)N_TOK * DIM];     // LayerNorm output fp16 (A for Qproj + residual)
__device__ __half g_q[(size_t)N_TOK * DIM];      // Q projection fp16
__device__ __half g_kv[BATCH * MCTX * 2 * DIM];  // K|V combined: row m, cols [0,512)=K, [512,1024)=V
__device__ __half g_att[(size_t)N_TOK * DIM];    // attention out fp16
__device__ __half g_ctx[BATCH * MCTX * CDIM];    // context fp16
__device__ __half g_wt[2 * CDIM * DIM + 2 * DIM * DIM]; // WkT,WvT,WqT,WoutT fp16, K-major [N][K]
__device__ float  g_bkv[2 * DIM];                // bk || bv

#define WT_WK 0
#define WT_WV (CDIM * DIM)
#define WT_WQ (2 * CDIM * DIM)
#define WT_WOUT (2 * CDIM * DIM + DIM * DIM)

// ---------------- helpers ----------------
__device__ __forceinline__ void mma16(float* c, const uint32_t* a, const uint32_t* b) {
    asm volatile(
        "mma.sync.aligned.m16n8k16.row.col.f32.f16.f16.f32 "
        "{%0,%1,%2,%3},{%4,%5,%6,%7},{%8,%9},{%0,%1,%2,%3};"
        : "+f"(c[0]), "+f"(c[1]), "+f"(c[2]), "+f"(c[3])
        : "r"(a[0]), "r"(a[1]), "r"(a[2]), "r"(a[3]), "r"(b[0]), "r"(b[1]));
}

__device__ __forceinline__ void ldsm4(uint32_t* r, const __half* p) {
    uint32_t a = (uint32_t)__cvta_generic_to_shared(p);
    asm volatile("ldmatrix.sync.aligned.m8n8.x4.shared.b16 {%0,%1,%2,%3}, [%4];"
        : "=r"(r[0]), "=r"(r[1]), "=r"(r[2]), "=r"(r[3]) : "r"(a));
}

// transposed ldmatrix: fragment of the TRANSPOSED 8x8 tiles (for row-major V as mma B)
__device__ __forceinline__ void ldsm4t(uint32_t* r, const __half* p) {
    uint32_t a = (uint32_t)__cvta_generic_to_shared(p);
    asm volatile("ldmatrix.sync.aligned.m8n8.x4.trans.shared.b16 {%0,%1,%2,%3}, [%4];"
        : "=r"(r[0]), "=r"(r[1]), "=r"(r[2]), "=r"(r[3]) : "r"(a));
}

__device__ __forceinline__ void cpa16(void* dst, const void* src) {
    uint32_t d = (uint32_t)__cvta_generic_to_shared(dst);
    asm volatile("cp.async.cg.shared.global [%0], [%1], 16;" :: "r"(d), "l"(src));
}
__device__ __forceinline__ void cp_commit() { asm volatile("cp.async.commit_group;"); }
template <int NN>
__device__ __forceinline__ void cp_wait() { asm volatile("cp.async.wait_group %0;" :: "n"(NN)); }

__device__ __forceinline__ uint32_t packh2(float lo, float hi) {
    __half2 h = __floats2half2_rn(lo, hi);
    return *(uint32_t*)&h;
}
__device__ __forceinline__ uint32_t ex2h2(uint32_t x) {
    uint32_t r;
    asm("ex2.approx.f16x2 %0, %1;" : "=r"(r) : "r"(x));
    return r;
}
__device__ __forceinline__ float ex2f(float x) {
    float r;
    asm("ex2.approx.f32 %0, %1;" : "=f"(r) : "f"(x));
    return r;
}

// ---------------- fp16 convert kernels ----------------
__global__ __launch_bounds__(256) void cvt_h_kernel(
    const float* __restrict__ src, __half* __restrict__ dst, int n)
{
    int i = blockIdx.x * blockDim.x + threadIdx.x;
    int stride = gridDim.x * blockDim.x;
    for (; i < n; i += stride) dst[i] = __float2half_rn(src[i]);
}

// merged transpose + fp16 for the 4 weights: dst[n][k] = h(src[k][n])
__global__ __launch_bounds__(256) void cvt_t4_kernel(
    const float* __restrict__ s0, const float* __restrict__ s1,
    const float* __restrict__ s2, const float* __restrict__ s3,
    __half* __restrict__ wt)
{
    __shared__ float t[32][33];
    int z = blockIdx.z;
    const float* src = (z == 0) ? s0 : (z == 1) ? s1 : (z == 2) ? s2 : s3;
    int Kd = (z < 2) ? CDIM : DIM;
    size_t doff = (z == 0) ? WT_WK : (z == 1) ? WT_WV : (z == 2) ? WT_WQ : (size_t)WT_WOUT;
    int k0 = blockIdx.x * 32, n0 = blockIdx.y * 32;
    if (k0 >= Kd) return;
    __half* dst = wt + doff;
    int tx = threadIdx.x & 31, ty = threadIdx.x >> 5;
#pragma unroll
    for (int i = ty; i < 32; i += 8)
        t[i][tx] = src[(size_t)(k0 + i) * DIM + n0 + tx];
    __syncthreads();
#pragma unroll
    for (int i = ty; i < 32; i += 8)
        dst[(size_t)(n0 + i) * Kd + k0 + tx] = __float2half_rn(t[tx][i]);
}

__global__ void bias_cat_kernel(const float* __restrict__ bk, const float* __restrict__ bv,
                                float* __restrict__ dst)
{
    int i = threadIdx.x + blockIdx.x * blockDim.x;
    if (i < DIM) dst[i] = bk[i];
    else if (i < 2 * DIM) dst[i] = bv[i - DIM];
}

// ---------------- LayerNorm: one warp per row; writes fp16 only ----------------
__global__ __launch_bounds__(256) void ln_kernel(
    const float* __restrict__ x, const float* __restrict__ g,
    const float* __restrict__ b, __half* __restrict__ out_h)
{
    int row = blockIdx.x * 8 + (threadIdx.x >> 5);
    int lane = threadIdx.x & 31;
    const float4* xp = (const float4*)(x + (size_t)row * DIM);
    float4 v[4];
    float s = 0.f;
#pragma unroll
    for (int j = 0; j < 4; j++) {
        v[j] = xp[lane + j * 32];
        s += v[j].x + v[j].y + v[j].z + v[j].w;
    }
#pragma unroll
    for (int o = 16; o; o >>= 1) s += __shfl_xor_sync(0xffffffffu, s, o);
    float mu = s * (1.f / DIM);
    float s2 = 0.f;
#pragma unroll
    for (int j = 0; j < 4; j++) {
        float dx;
        dx = v[j].x - mu; s2 += dx * dx;
        dx = v[j].y - mu; s2 += dx * dx;
        dx = v[j].z - mu; s2 += dx * dx;
        dx = v[j].w - mu; s2 += dx * dx;
    }
#pragma unroll
    for (int o = 16; o; o >>= 1) s2 += __shfl_xor_sync(0xffffffffu, s2, o);
    float rstd = rsqrtf(s2 * (1.f / DIM) + 1e-5f);
    const float4* gp = (const float4*)g;
    const float4* bp = (const float4*)b;
    __half2* ohp = (__half2*)(out_h + (size_t)row * DIM);
#pragma unroll
    for (int j = 0; j < 4; j++) {
        int idx = lane + j * 32;
        float4 gg = gp[idx], bb = bp[idx];
        float ox = (v[j].x - mu) * rstd * gg.x + bb.x;
        float oy = (v[j].y - mu) * rstd * gg.y + bb.y;
        float oz = (v[j].z - mu) * rstd * gg.z + bb.z;
        float ow = (v[j].w - mu) * rstd * gg.w + bb.w;
        ohp[idx * 2]     = __floats2half2_rn(ox, oy);
        ohp[idx * 2 + 1] = __floats2half2_rn(oz, ow);
    }
}

// ---------------- fp16 GEMM: 3-stage cp.async ring, ldmatrix, 64x64 warp tiles -----
// out = A[M,K] @ Bt[N,K]^T + bias (+fp16 resid). A, Bt fp16 K-major.
// Block 128x128, 128 threads, 4 warps (2m x 2n). One __syncthreads per ktile.
#define GH_OP 5120                 // halves per operand per stage (128 rows x 40)
#define GH_STAGE (2 * GH_OP)       // halves per stage (A + B)
#define GH_SMEM (3 * GH_STAGE * 2) // bytes: 61440

extern __shared__ __half gh_sm[];
__global__ __launch_bounds__(128, 3) void gemm_h(
    const __half* __restrict__ A, const __half* __restrict__ Bt,
    const float* __restrict__ bias, const __half* __restrict__ resid,
    __half* __restrict__ outh, float* __restrict__ outf, int K, int Nc)
{
    const int tid = threadIdx.x;
    const int w = tid >> 5, lane = tid & 31, grp = lane >> 2, tq = lane & 3;
    const int wm = (w & 1) * 64, wn = (w >> 1) * 64;
    const int m0 = blockIdx.y * 128, n0 = blockIdx.x * 128;
    const int lr = lane & 7, sect = lane >> 3;   // ldmatrix addressing
    const int sa_row = (sect & 1) * 8 + lr, sa_col = (sect >> 1) * 8;
    const int sb_row = (sect >> 1) * 8 + lr, sb_col = (sect & 1) * 8;

    float acc[4][8][4];
#pragma unroll
    for (int i = 0; i < 4; i++)
#pragma unroll
        for (int j = 0; j < 8; j++)
#pragma unroll
            for (int r = 0; r < 4; r++) acc[i][j][r] = 0.f;

    auto load_tile = [&](int st, int k0) {
        __half* Ab = gh_sm + st * GH_STAGE;
        __half* Bb = Ab + GH_OP;
#pragma unroll
        for (int j = 0; j < 4; j++) {
            int lin = tid + j * 128;
            int row = lin >> 2, seg = lin & 3;
            cpa16(Ab + row * 40 + seg * 8, A + (size_t)(m0 + row) * K + k0 + seg * 8);
        }
#pragma unroll
        for (int j = 0; j < 4; j++) {
            int lin = tid + j * 128;
            int row = lin >> 2, seg = lin & 3;
            cpa16(Bb + row * 40 + seg * 8, Bt + (size_t)(n0 + row) * K + k0 + seg * 8);
        }
        cp_commit();
    };

    load_tile(0, 0);
    load_tile(1, 32);

    const int KT = K / 32;
#pragma unroll 1
    for (int kt = 0; kt < KT; kt++) {
        if (kt == KT - 1) cp_wait<0>(); else cp_wait<1>();
        __syncthreads();
        const __half* Ab = gh_sm + (kt % 3) * GH_STAGE;
        const __half* Bb = Ab + GH_OP;
#pragma unroll
        for (int ks = 0; ks < 2; ks++) {
            uint32_t a[4][4], b[8][2];
#pragma unroll
            for (int mf = 0; mf < 4; mf++)
                ldsm4(a[mf], Ab + (wm + mf * 16 + sa_row) * 40 + ks * 16 + sa_col);
#pragma unroll
            for (int nf2 = 0; nf2 < 4; nf2++) {
                uint32_t t[4];
                ldsm4(t, Bb + (wn + nf2 * 16 + sb_row) * 40 + ks * 16 + sb_col);
                b[2 * nf2][0] = t[0]; b[2 * nf2][1] = t[1];
                b[2 * nf2 + 1][0] = t[2]; b[2 * nf2 + 1][1] = t[3];
            }
#pragma unroll
            for (int mf = 0; mf < 4; mf++)
#pragma unroll
                for (int nf = 0; nf < 8; nf++)
                    mma16(acc[mf][nf], a[mf], b[nf]);
        }
        // loads for kt+2 go into stage (kt+2)%3, last read at iter kt-1 (pre-barrier)
        if (kt + 2 < KT) load_tile((kt + 2) % 3, (kt + 2) * 32);
    }

    // epilogue
#pragma unroll
    for (int mf = 0; mf < 4; mf++) {
        int r = m0 + wm + mf * 16 + grp;
#pragma unroll
        for (int nf = 0; nf < 8; nf++) {
            int c = n0 + wn + nf * 8 + tq * 2;
            float b0 = bias[c], b1 = bias[c + 1];
            float v0 = acc[mf][nf][0] + b0, v1 = acc[mf][nf][1] + b1;
            float v2 = acc[mf][nf][2] + b0, v3 = acc[mf][nf][3] + b1;
            if (outh) {
                *(__half2*)&outh[(size_t)r * Nc + c]       = __floats2half2_rn(v0, v1);
                *(__half2*)&outh[(size_t)(r + 8) * Nc + c] = __floats2half2_rn(v2, v3);
            } else {
                float2 r0 = __half22float2(*(const __half2*)&resid[(size_t)r * Nc + c]);
                float2 r1 = __half22float2(*(const __half2*)&resid[(size_t)(r + 8) * Nc + c]);
                v0 += r0.x; v1 += r0.y;
                v2 += r1.x; v3 += r1.y;
                *(float2*)&outf[(size_t)r * Nc + c]       = make_float2(v0, v1);
                *(float2*)&outf[(size_t)(r + 8) * Nc + c] = make_float2(v2, v3);
            }
        }
    }
}

// ---------------- fused attention (fp16): 256-query tile, flash online softmax ------
// 512 threads, 16 warps; warp owns 16 q-rows x 256 ctx in 4 chunks of 64.
// V kept ROW-MAJOR [ctx][hd] in smem; O-mma B-fragments built with ldmatrix.trans
// (no transpose prologue). All of Q/K/V arrive via cp.async.
#define ATT_SMEM (3 * 256 * 72 * 2)   // 110592 bytes

extern __shared__ __half att_sm[];
__global__ __launch_bounds__(512, 1) void attn_kernel(
    const __half* __restrict__ Q, const __half* __restrict__ KV,
    __half* __restrict__ O)
{
    __half* Qs = att_sm;               // [256][72]
    __half* Ks = att_sm + 256 * 72;    // [256][72]
    __half* Vs = att_sm + 2 * 256 * 72; // [256][72] row-major (ctx, hd)

    int b = blockIdx.z, h = blockIdx.y, qt = blockIdx.x;
    int tid = threadIdx.x, w = tid >> 5, lane = tid & 31, grp = lane >> 2, tq = lane & 3;
    const int lr = lane & 7, sect = lane >> 3;
    const int sa_row = (sect & 1) * 8 + lr, sa_col = (sect >> 1) * 8;
    const int sb_row = (sect >> 1) * 8 + lr, sb_col = (sect & 1) * 8;
    const int sv_row = (sect & 1) * 8 + lr, sv_col = (sect >> 1) * 8;  // trans tiles
    size_t qbase  = ((size_t)(b * NB + qt * 256)) * DIM + h * HD;
    size_t kvbase = ((size_t)(b * MCTX)) * (2 * DIM) + h * HD;

    // Q, K, V all via cp.async (8-half segments); 512 threads
#pragma unroll
    for (int j = 0; j < 4; j++) {
        int lin = tid + j * 512;
        int m = lin >> 3, seg = lin & 7;
        cpa16(Qs + m * 72 + seg * 8, Q + qbase + (size_t)m * DIM + seg * 8);
    }
#pragma unroll
    for (int j = 0; j < 4; j++) {
        int lin = tid + j * 512;
        int m = lin >> 3, seg = lin & 7;
        cpa16(Ks + m * 72 + seg * 8, KV + kvbase + (size_t)m * (2 * DIM) + seg * 8);
    }
#pragma unroll
    for (int j = 0; j < 4; j++) {
        int lin = tid + j * 512;
        int m = lin >> 3, seg = lin & 7;
        cpa16(Vs + m * 72 + seg * 8, KV + kvbase + DIM + (size_t)m * (2 * DIM) + seg * 8);
    }
    cp_commit();
    cp_wait<0>();
    __syncthreads();

    const int r0 = w * 16;

    float o[8][4];
#pragma unroll
    for (int f = 0; f < 8; f++)
#pragma unroll
        for (int r = 0; r < 4; r++) o[f][r] = 0.f;
    float mA = -1e30f, mB = -1e30f, sA = 0.f, sB = 0.f;

#pragma unroll 1
    for (int c = 0; c < 4; c++) {
        // ---- S chunk = Q @ K[c*64 : c*64+64]^T
        float s[8][4];
#pragma unroll
        for (int f = 0; f < 8; f++)
#pragma unroll
            for (int r = 0; r < 4; r++) s[f][r] = 0.f;

#pragma unroll
        for (int ks = 0; ks < 4; ks++) {
            uint32_t a[4];
            ldsm4(a, Qs + (r0 + sa_row) * 72 + ks * 16 + sa_col);
#pragma unroll
            for (int fp = 0; fp < 4; fp++) {
                uint32_t t[4];
                ldsm4(t, Ks + (c * 64 + fp * 16 + sb_row) * 72 + ks * 16 + sb_col);
                mma16(s[2 * fp], a, t);
                mma16(s[2 * fp + 1], a, t + 2);
            }
        }

        // ---- online max + rescale
        float cA = -1e30f, cB = -1e30f;
#pragma unroll
        for (int f = 0; f < 8; f++) {
            cA = fmaxf(cA, fmaxf(s[f][0], s[f][1]));
            cB = fmaxf(cB, fmaxf(s[f][2], s[f][3]));
        }
        cA = fmaxf(cA, __shfl_xor_sync(0xffffffffu, cA, 1));
        cA = fmaxf(cA, __shfl_xor_sync(0xffffffffu, cA, 2));
        cB = fmaxf(cB, __shfl_xor_sync(0xffffffffu, cB, 1));
        cB = fmaxf(cB, __shfl_xor_sync(0xffffffffu, cB, 2));
        float nA = fmaxf(mA, cA * ATT_C2);
        float nB = fmaxf(mB, cB * ATT_C2);
        float fA = ex2f(mA - nA);
        float fB = ex2f(mB - nB);
        mA = nA; mB = nB;
        sA *= fA; sB *= fB;
#pragma unroll
        for (int f = 0; f < 8; f++) {
            o[f][0] *= fA; o[f][1] *= fA;
            o[f][2] *= fB; o[f][3] *= fB;
        }

        // ---- exp2 to fp16 (unnormalized P = A-fragments) + partial sums
        uint32_t ph[8][2];
#pragma unroll
        for (int f = 0; f < 8; f++) {
            ph[f][0] = ex2h2(packh2(fmaf(s[f][0], ATT_C2, -nA), fmaf(s[f][1], ATT_C2, -nA)));
            ph[f][1] = ex2h2(packh2(fmaf(s[f][2], ATT_C2, -nB), fmaf(s[f][3], ATT_C2, -nB)));
            float2 eA = __half22float2(*(__half2*)&ph[f][0]);
            float2 eB = __half22float2(*(__half2*)&ph[f][1]);
            sA += eA.x + eA.y;
            sB += eB.x + eB.y;
        }

        // ---- O += P_chunk @ V_chunk (B-frags via ldmatrix.trans on row-major V)
#pragma unroll
        for (int kt = 0; kt < 4; kt++) {
            uint32_t a[4];
            a[0] = ph[2 * kt][0];
            a[1] = ph[2 * kt][1];
            a[2] = ph[2 * kt + 1][0];
            a[3] = ph[2 * kt + 1][1];
#pragma unroll
            for (int f2p = 0; f2p < 4; f2p++) {
                uint32_t t[4];
                ldsm4t(t, Vs + (c * 64 + kt * 16 + sv_row) * 72 + f2p * 16 + sv_col);
                mma16(o[2 * f2p], a, t);
                mma16(o[2 * f2p + 1], a, t + 2);
            }
        }
    }

    // ---- final row sums (quad reduce) + normalize + store
    sA += __shfl_xor_sync(0xffffffffu, sA, 1);
    sA += __shfl_xor_sync(0xffffffffu, sA, 2);
    sB += __shfl_xor_sync(0xffffffffu, sB, 1);
    sB += __shfl_xor_sync(0xffffffffu, sB, 2);
    const float iA = 1.f / sA, iB = 1.f / sB;

#pragma unroll
    for (int f2 = 0; f2 < 8; f2++) {
        int col = f2 * 8 + tq * 2;
        *(__half2*)&O[qbase + (size_t)(r0 + grp) * DIM + col] =
            __floats2half2_rn(o[f2][0] * iA, o[f2][1] * iA);
        *(__half2*)&O[qbase + (size_t)(r0 + grp + 8) * DIM + col] =
            __floats2half2_rn(o[f2][2] * iB, o[f2][3] * iB);
    }
}

// ---------------- launcher ----------------
extern "C" void kernel_launch(void* const* d_in, const int* in_sizes, int n_in,
                              void* d_out, int out_size)
{
    const float* features = (const float*)d_in[0];
    // d_in[1] = batch_indices: sorted, equal counts -> batch = row / NB (arithmetic)
    const float* context = (const float*)d_in[2];
    const float* Wq = (const float*)d_in[3];
    const float* bq = (const float*)d_in[4];
    const float* Wk = (const float*)d_in[5];
    const float* bk = (const float*)d_in[6];
    const float* Wv = (const float*)d_in[7];
    const float* bv = (const float*)d_in[8];
    const float* Wout = (const float*)d_in[9];
    const float* bout = (const float*)d_in[10];
    const float* ln_g = (const float*)d_in[11];
    const float* ln_b = (const float*)d_in[12];
    float* out = (float*)d_out;

    __half *fh_p, *q_p, *kv_p, *att_p, *ctx_p, *wt_p;
    float* bkv_p;
    cudaGetSymbolAddress((void**)&fh_p, g_fh);
    cudaGetSymbolAddress((void**)&q_p, g_q);
    cudaGetSymbolAddress((void**)&kv_p, g_kv);
    cudaGetSymbolAddress((void**)&att_p, g_att);
    cudaGetSymbolAddress((void**)&ctx_p, g_ctx);
    cudaGetSymbolAddress((void**)&wt_p, g_wt);
    cudaGetSymbolAddress((void**)&bkv_p, g_bkv);

    cudaFuncSetAttribute(gemm_h, cudaFuncAttributeMaxDynamicSharedMemorySize, GH_SMEM);
    cudaFuncSetAttribute(attn_kernel, cudaFuncAttributeMaxDynamicSharedMemorySize, ATT_SMEM);

    cvt_h_kernel<<<2048, 256>>>(context, ctx_p, BATCH * MCTX * CDIM);
    cvt_t4_kernel<<<dim3(CDIM / 32, DIM / 32, 4), 256>>>(Wk, Wv, Wq, Wout, wt_p);
    bias_cat_kernel<<<4, 256>>>(bk, bv, bkv_p);

    // 1. LayerNorm (fp16 output; also the residual source)
    ln_kernel<<<N_TOK / 8, 256>>>(features, ln_g, ln_b, fh_p);
    // 2. K+V projection in ONE gemm: (2048, 768) @ (768, 1024) -> g_kv
    gemm_h<<<dim3((2 * DIM) / 128, (BATCH * MCTX) / 128), 128, GH_SMEM>>>(
        ctx_p, wt_p + WT_WK, bkv_p, nullptr, kv_p, nullptr, CDIM, 2 * DIM);
    // 3. Q projection: (131072, 512) @ (512, 512)
    gemm_h<<<dim3(DIM / 128, N_TOK / 128), 128, GH_SMEM>>>(
        fh_p, wt_p + WT_WQ, bq, nullptr, q_p, nullptr, DIM, DIM);
    // 4. Attention (256-q tile, ldmatrix.trans V, 512 threads)
    attn_kernel<<<dim3(NB / 256, NH, BATCH), 512, ATT_SMEM>>>(q_p, kv_p, att_p);
    // 5. Output projection + bias + residual (fp32 out, fp16 residual)
    gemm_h<<<dim3(DIM / 128, N_TOK / 128), 128, GH_SMEM>>>(
        att_p, wt_p + WT_WOUT, bout, fh_p, nullptr, out, DIM, DIM);
}